// round 6
// baseline (speedup 1.0000x reference)
#include <cuda_runtime.h>
#include <math.h>

static const int T  = 2048;
static const int C  = 1024;
static const int NH = 16;
static const int HS = 64;
#define EPS_GN 0.00064f

typedef unsigned long long u64;

// ---------------- f32x2 packed helpers (sm_103a FFMA2 path) ----------------
__device__ __forceinline__ u64 fma2(u64 a, u64 b, u64 c) {
    u64 d; asm("fma.rn.f32x2 %0, %1, %2, %3;" : "=l"(d) : "l"(a), "l"(b), "l"(c)); return d;
}
__device__ __forceinline__ u64 mul2(u64 a, u64 b) {
    u64 d; asm("mul.rn.f32x2 %0, %1, %2;" : "=l"(d) : "l"(a), "l"(b)); return d;
}
__device__ __forceinline__ u64 add2(u64 a, u64 b) {
    u64 d; asm("add.rn.f32x2 %0, %1, %2;" : "=l"(d) : "l"(a), "l"(b)); return d;
}
__device__ __forceinline__ u64 pack2(float lo, float hi) {
    u64 d; asm("mov.b64 %0, {%1, %2};" : "=l"(d) : "f"(lo), "f"(hi)); return d;
}
__device__ __forceinline__ float2 unpack2(u64 v) {
    float2 r; asm("mov.b64 {%0, %1}, %2;" : "=f"(r.x), "=f"(r.y) : "l"(v)); return r;
}
__device__ __forceinline__ void cp16(unsigned s, const float* g) {
    asm volatile("cp.async.ca.shared.global [%0], [%1], 16;" :: "r"(s), "l"(g));
}

// ---------------- scratch ----------------
__device__ float g_scratch[(size_t)17 * 2048 * 1024 + (size_t)2048 * 288];

// ---------------- K1: token shift + 6-way mix ----------------
__global__ void k_shift_mix(const float* __restrict__ x, const float* __restrict__ x_prev,
                            const int* __restrict__ cu, int ncu,
                            const float* __restrict__ mr, const float* __restrict__ mw,
                            const float* __restrict__ mk, const float* __restrict__ mv,
                            const float* __restrict__ ma, const float* __restrict__ mg,
                            float* __restrict__ oxr, float* __restrict__ oxw,
                            float* __restrict__ oxk, float* __restrict__ oxv,
                            float* __restrict__ oxa, float* __restrict__ oxg) {
    const int t = blockIdx.x;
    int kind = (t == 0) ? 1 : 0;
    int prow = 0;
    for (int i = 0; i + 1 < ncu; i++) if (cu[i] == t) { kind = 2; prow = i; }
    const int c = threadIdx.x * 4;
    const size_t off = (size_t)t * C + c;
    float4 xc = *(const float4*)(x + off);
    float4 pv;
    if (kind == 0)      pv = *(const float4*)(x + off - C);
    else if (kind == 2) pv = *(const float4*)(x_prev + (size_t)prow * C + c);
    else                pv = make_float4(0.f, 0.f, 0.f, 0.f);
    float4 dx = make_float4(pv.x - xc.x, pv.y - xc.y, pv.z - xc.z, pv.w - xc.w);
#define MIXOUT(dst, m) { \
    float4 mm = *(const float4*)((m) + c); \
    float4 r_ = make_float4(fmaf(dx.x, mm.x, xc.x), fmaf(dx.y, mm.y, xc.y), \
                            fmaf(dx.z, mm.z, xc.z), fmaf(dx.w, mm.w, xc.w)); \
    *(float4*)((dst) + off) = r_; }
    MIXOUT(oxr, mr) MIXOUT(oxw, mw) MIXOUT(oxk, mk)
    MIXOUT(oxv, mv) MIXOUT(oxa, ma) MIXOUT(oxg, mg)
#undef MIXOUT
}

// ---------------- K2: fp32 NT GEMM via FFMA2, 128x128 tile, BK=16, double-buffered ----
__global__ void __launch_bounds__(256, 2) k_gemm_nt(const float* __restrict__ A,
                                                    const float* __restrict__ B,
                                                    float* __restrict__ Cg) {
    __shared__ float As[2][16][128];
    __shared__ float Bs[2][16][128];
    const int bm = blockIdx.y * 128;
    const int bn = blockIdx.x * 128;
    const int tid = threadIdx.x;
    const int tx = tid & 15, ty = tid >> 4;
    const int lr = tid >> 1;
    const int lk = (tid & 1) * 8;

    const float* Ap = A + (size_t)(bm + lr) * C + lk;
    const float* Bp = B + (size_t)(bn + lr) * C + lk;

    u64 acc[4][8];
#pragma unroll
    for (int p = 0; p < 4; p++)
#pragma unroll
        for (int j = 0; j < 8; j++) acc[p][j] = 0ull;

    float4 av0 = *(const float4*)Ap;
    float4 av1 = *(const float4*)(Ap + 4);
    float4 bv0 = *(const float4*)Bp;
    float4 bv1 = *(const float4*)(Bp + 4);

#define STS_TILE(bf) { \
    As[bf][lk+0][lr]=av0.x; As[bf][lk+1][lr]=av0.y; As[bf][lk+2][lr]=av0.z; As[bf][lk+3][lr]=av0.w; \
    As[bf][lk+4][lr]=av1.x; As[bf][lk+5][lr]=av1.y; As[bf][lk+6][lr]=av1.z; As[bf][lk+7][lr]=av1.w; \
    Bs[bf][lk+0][lr]=bv0.x; Bs[bf][lk+1][lr]=bv0.y; Bs[bf][lk+2][lr]=bv0.z; Bs[bf][lk+3][lr]=bv0.w; \
    Bs[bf][lk+4][lr]=bv1.x; Bs[bf][lk+5][lr]=bv1.y; Bs[bf][lk+6][lr]=bv1.z; Bs[bf][lk+7][lr]=bv1.w; }

    STS_TILE(0)
    __syncthreads();

    const int NIT = C / 16;
    for (int kt = 0; kt < NIT; kt++) {
        if (kt + 1 < NIT) {
            const float* Ap2 = Ap + (kt + 1) * 16;
            const float* Bp2 = Bp + (kt + 1) * 16;
            av0 = *(const float4*)Ap2; av1 = *(const float4*)(Ap2 + 4);
            bv0 = *(const float4*)Bp2; bv1 = *(const float4*)(Bp2 + 4);
        }
        const int buf = kt & 1;
#pragma unroll
        for (int kk = 0; kk < 16; kk++) {
            float4 a0 = *(const float4*)&As[buf][kk][ty * 8];
            float4 a1 = *(const float4*)&As[buf][kk][ty * 8 + 4];
            float4 b0 = *(const float4*)&Bs[buf][kk][tx * 8];
            float4 b1 = *(const float4*)&Bs[buf][kk][tx * 8 + 4];
            u64 ap[4];
            ap[0] = pack2(a0.x, a0.y); ap[1] = pack2(a0.z, a0.w);
            ap[2] = pack2(a1.x, a1.y); ap[3] = pack2(a1.z, a1.w);
            u64 bd[8];
            bd[0] = pack2(b0.x, b0.x); bd[1] = pack2(b0.y, b0.y);
            bd[2] = pack2(b0.z, b0.z); bd[3] = pack2(b0.w, b0.w);
            bd[4] = pack2(b1.x, b1.x); bd[5] = pack2(b1.y, b1.y);
            bd[6] = pack2(b1.z, b1.z); bd[7] = pack2(b1.w, b1.w);
#pragma unroll
            for (int p = 0; p < 4; p++)
#pragma unroll
                for (int j = 0; j < 8; j++)
                    acc[p][j] = fma2(ap[p], bd[j], acc[p][j]);
        }
        if (kt + 1 < NIT) {
            STS_TILE((kt + 1) & 1)
        }
        __syncthreads();
    }
#undef STS_TILE

#pragma unroll
    for (int p = 0; p < 4; p++) {
        float lo[8], hi[8];
#pragma unroll
        for (int j = 0; j < 8; j++) {
            float2 u = unpack2(acc[p][j]);
            lo[j] = u.x; hi[j] = u.y;
        }
        float* row0 = Cg + (size_t)(bm + ty * 8 + 2 * p) * C + bn + tx * 8;
        float* row1 = row0 + C;
        *(float4*)row0       = make_float4(lo[0], lo[1], lo[2], lo[3]);
        *(float4*)(row0 + 4) = make_float4(lo[4], lo[5], lo[6], lo[7]);
        *(float4*)row1       = make_float4(hi[0], hi[1], hi[2], hi[3]);
        *(float4*)(row1 + 4) = make_float4(hi[4], hi[5], hi[6], hi[7]);
    }
}

// ---------------- K3: stage-1 LoRA GEMM ----------------
template <int KO, int ACT>
__global__ void __launch_bounds__(256) k_stage1(const float* __restrict__ X,
                                                const float* __restrict__ W,
                                                float* __restrict__ out) {
    __shared__ float Xs[32][33];
    __shared__ float Ws[32][KO];
    const int t0 = blockIdx.x * 32;
    const int tid = threadIdx.x;
    const int j = tid % KO;
    const int tg = tid / KO;
    const int RPT = 256 / KO;
    const int NT = 32 / RPT;
    float acc[NT];
#pragma unroll
    for (int tt = 0; tt < NT; tt++) acc[tt] = 0.f;

    for (int cb = 0; cb < C; cb += 32) {
#pragma unroll
        for (int i = tid; i < 32 * 32; i += 256)
            Xs[i >> 5][i & 31] = X[(size_t)(t0 + (i >> 5)) * C + cb + (i & 31)];
#pragma unroll
        for (int i = tid; i < 32 * KO; i += 256)
            Ws[i / KO][i % KO] = W[(size_t)(cb + i / KO) * KO + (i % KO)];
        __syncthreads();
#pragma unroll
        for (int cc = 0; cc < 32; cc++) {
            float wv = Ws[cc][j];
#pragma unroll
            for (int tt = 0; tt < NT; tt++)
                acc[tt] = fmaf(Xs[tg * NT + tt][cc], wv, acc[tt]);
        }
        __syncthreads();
    }
#pragma unroll
    for (int tt = 0; tt < NT; tt++) {
        float val = acc[tt];
        if (ACT == 1) val = tanhf(val);
        else if (ACT == 2) val = 1.f / (1.f + expf(-val));
        out[(size_t)(t0 + tg * NT + tt) * KO + j] = val;
    }
}

// ---------------- K4: stage-2 LoRA GEMM + fused epilogue ----------------
template <int KI, int EPI>
__global__ void __launch_bounds__(128) k_stage2(const float* __restrict__ Hh,
                                                const float* __restrict__ W2,
                                                const float* __restrict__ bias,
                                                const float* __restrict__ e1,
                                                const float* __restrict__ e2,
                                                float* __restrict__ out) {
    __shared__ float Hs[16][KI];
    const int tb = blockIdx.y * 16;
    const int o = blockIdx.x * 128 + threadIdx.x;
    for (int i = threadIdx.x; i < 16 * KI; i += 128)
        Hs[i / KI][i % KI] = Hh[(size_t)(tb + i / KI) * KI + (i % KI)];
    __syncthreads();
    float acc[16];
#pragma unroll
    for (int t = 0; t < 16; t++) acc[t] = 0.f;
#pragma unroll 8
    for (int cdx = 0; cdx < KI; cdx++) {
        float wv = W2[(size_t)cdx * C + o];
#pragma unroll
        for (int t = 0; t < 16; t++)
            acc[t] = fmaf(Hs[t][cdx], wv, acc[t]);
    }
    float bv = (EPI == 3) ? 0.f : bias[o];
#pragma unroll
    for (int t = 0; t < 16; t++) {
        size_t idx = (size_t)(tb + t) * C + o;
        float zv = acc[t] + bv;
        float res;
        if (EPI == 0) {
            float xn = -zv;
            float sp = (xn > 20.f) ? xn : log1pf(expf(xn));
            res = expf(-expf(-sp - 0.5f));
        } else if (EPI == 1) {
            res = 1.f / (1.f + expf(-zv));
        } else if (EPI == 2) {
            float sg = 1.f / (1.f + expf(-zv));
            float vr = e1[idx];
            res = fmaf(e2[idx] - vr, sg, vr);
        } else {
            res = zv;
        }
        out[idx] = res;
    }
}

// ---------------- K5: scan-input prep ----------------
__global__ void k_prep(const float* __restrict__ kin, const float* __restrict__ ain,
                       const float* __restrict__ kkw, const float* __restrict__ kaw,
                       float* __restrict__ aab, float* __restrict__ bbb,
                       float* __restrict__ kadj) {
    const int t = blockIdx.x;
    const int tid = threadIdx.x;
    const int cbase = tid * 4;
    const size_t idx = (size_t)t * C + cbase;
    float4 kv = *(const float4*)(kin + idx);
    float4 av = *(const float4*)(ain + idx);
    float4 kw = *(const float4*)(kkw + cbase);
    float4 aw = *(const float4*)(kaw + cbase);
    float4 kk = make_float4(kv.x * kw.x, kv.y * kw.y, kv.z * kw.z, kv.w * kw.w);
    float ss = kk.x * kk.x + kk.y * kk.y + kk.z * kk.z + kk.w * kk.w;
#pragma unroll
    for (int off = 8; off > 0; off >>= 1)
        ss += __shfl_xor_sync(0xffffffffu, ss, off);
    float inv = 1.f / fmaxf(sqrtf(ss), 1e-12f);
    float4 kn = make_float4(kk.x * inv, kk.y * inv, kk.z * inv, kk.w * inv);
    *(float4*)(aab + idx) = make_float4(-kn.x, -kn.y, -kn.z, -kn.w);
    *(float4*)(bbb + idx) = make_float4(kn.x * av.x, kn.y * av.y, kn.z * av.z, kn.w * av.w);
    *(float4*)(kadj + idx) = make_float4(
        kv.x * fmaf(av.x - 1.f, aw.x, 1.f),
        kv.y * fmaf(av.y - 1.f, aw.y, 1.f),
        kv.z * fmaf(av.z - 1.f, aw.z, 1.f),
        kv.w * fmaf(av.w - 1.f, aw.w, 1.f));
}

// ---------------- K6: RWKV-7 serial scan (cp.async ring + FFMA2, union-free) ----------
#define D_RING 8
#define D_LAG  6

// Load 16 floats from smem as 4x float4 and pack into 8 u64 (no local-array casts!)
#define LD_PACK(U, base) { \
    float4 f0_ = *(const float4*)((base));      \
    float4 f1_ = *(const float4*)((base) + 4);  \
    float4 f2_ = *(const float4*)((base) + 8);  \
    float4 f3_ = *(const float4*)((base) + 12); \
    U[0] = pack2(f0_.x, f0_.y); U[1] = pack2(f0_.z, f0_.w); \
    U[2] = pack2(f1_.x, f1_.y); U[3] = pack2(f1_.z, f1_.w); \
    U[4] = pack2(f2_.x, f2_.y); U[5] = pack2(f2_.z, f2_.w); \
    U[6] = pack2(f3_.x, f3_.y); U[7] = pack2(f3_.z, f3_.w); }

__global__ void __launch_bounds__(32) k_scan(const float* __restrict__ rb,
                                             const float* __restrict__ ewb,
                                             const float* __restrict__ aab,
                                             const float* __restrict__ bbb,
                                             const float* __restrict__ kb,
                                             const float* __restrict__ vb,
                                             const float* __restrict__ S0,
                                             float* __restrict__ y) {
    __shared__ float ring[D_RING][6 * HS];
    const int h  = blockIdx.x;
    const int vg = blockIdx.y;
    const int tid = threadIdx.x;
    const int jg = tid & 3;
    const int vr = tid >> 2;
    const int vrow = vg * 8 + vr;
    const int jb = jg * 16;

    u64 S[8];
    {
        const float* sb = S0 + (size_t)h * HS * HS + (size_t)vrow * HS + jb;
        LD_PACK(S, sb)
    }

    const int off16 = (tid & 15) << 2;
    const int arr0 = tid >> 4;
    const int arr1 = arr0 + 2;
    const int arr2 = arr0 + 4;
    const float* s0 = (arr0 == 0 ? rb  : ewb) + (size_t)h * HS + off16;
    const float* s1 = (arr1 == 2 ? aab : bbb) + (size_t)h * HS + off16;
    const float* s2 = (arr2 == 4 ? kb  : vb ) + (size_t)h * HS + off16;
    unsigned base_u = (unsigned)__cvta_generic_to_shared(&ring[0][0]);
    const unsigned d0 = base_u + (unsigned)(arr0 * HS + off16) * 4u;
    const unsigned d1 = base_u + (unsigned)(arr1 * HS + off16) * 4u;
    const unsigned d2 = base_u + (unsigned)(arr2 * HS + off16) * 4u;

#define ISSUE(step, slot) { \
    int st_ = (step) < T ? (step) : (T - 1); \
    size_t so_ = (size_t)st_ * C; \
    unsigned sb_ = (unsigned)(slot) * (6 * HS * 4); \
    cp16(d0 + sb_, s0 + so_); \
    cp16(d1 + sb_, s1 + so_); \
    cp16(d2 + sb_, s2 + so_); \
    asm volatile("cp.async.commit_group;"); }

#pragma unroll
    for (int s = 0; s < D_LAG; s++) ISSUE(s, s)

    float o_l = 0.f, os1 = 0.f, os2 = 0.f, os3 = 0.f;
    const size_t ybase = (size_t)h * HS + vrow;

    for (int t = 0; t < T; t++) {
        const int slot = t & (D_RING - 1);
        asm volatile("cp.async.wait_group %0;" :: "n"(D_LAG - 1));
        __syncwarp();

        if (t > 0 && jg == 0)
            y[(size_t)(t - 1) * C + ybase] = (o_l + os1) + (os2 + os3);

        const float* sp = &ring[slot][0];
        u64 Ru[8], Eu[8], Au[8], Bu[8], Ku[8];
        LD_PACK(Ru, sp + 0 * HS + jb)
        LD_PACK(Eu, sp + 1 * HS + jb)
        LD_PACK(Au, sp + 2 * HS + jb)
        LD_PACK(Bu, sp + 3 * HS + jb)
        LD_PACK(Ku, sp + 4 * HS + jb)
        const float vt = sp[5 * HS + vrow];

        ISSUE(t + D_LAG, (t + D_LAG) & (D_RING - 1))

        // sa = S . aa (16 local) — two parallel FFMA2 chains
        u64 sacc0 = mul2(S[0], Au[0]);
        u64 sacc1 = mul2(S[1], Au[1]);
#pragma unroll
        for (int q = 2; q < 8; q += 2) {
            sacc0 = fma2(S[q],     Au[q],     sacc0);
            sacc1 = fma2(S[q + 1], Au[q + 1], sacc1);
        }
        float2 sp2 = unpack2(add2(sacc0, sacc1));
        float sal = sp2.x + sp2.y;
        float sA = __shfl_xor_sync(0xffffffffu, sal, 1);
        float sB = __shfl_xor_sync(0xffffffffu, sal, 2);
        float sC = __shfl_xor_sync(0xffffffffu, sal, 3);

        // overlap shfl latency: pre = S*ew + vt*k
        u64 vt2 = pack2(vt, vt);
        u64 pre[8];
#pragma unroll
        for (int q = 0; q < 8; q++)
            pre[q] = fma2(S[q], Eu[q], mul2(vt2, Ku[q]));

        float sa = (sal + sA) + (sB + sC);
        u64 sa2 = pack2(sa, sa);

        u64 oa0 = 0ull, oa1 = 0ull;
#pragma unroll
        for (int q = 0; q < 8; q += 2) {
            S[q]     = fma2(sa2, Bu[q],     pre[q]);
            S[q + 1] = fma2(sa2, Bu[q + 1], pre[q + 1]);
            oa0 = fma2(S[q],     Ru[q],     oa0);
            oa1 = fma2(S[q + 1], Ru[q + 1], oa1);
        }
        float2 op2 = unpack2(add2(oa0, oa1));
        o_l = op2.x + op2.y;
        os1 = __shfl_xor_sync(0xffffffffu, o_l, 1);
        os2 = __shfl_xor_sync(0xffffffffu, o_l, 2);
        os3 = __shfl_xor_sync(0xffffffffu, o_l, 3);
    }
    if (jg == 0)
        y[(size_t)(T - 1) * C + ybase] = (o_l + os1) + (os2 + os3);
#undef ISSUE
}

// ---------------- K7: GroupNorm + bonus + gate ----------------
__global__ void k_gn(const float* __restrict__ y, const float* __restrict__ r,
                     const float* __restrict__ kadj, const float* __restrict__ v,
                     const float* __restrict__ gg, const float* __restrict__ rk,
                     const float* __restrict__ lnw, const float* __restrict__ lnb,
                     float* __restrict__ z) {
    const int t = blockIdx.x;
    const int tid = threadIdx.x;
    const int cbase = tid * 4;
    const size_t idx = (size_t)t * C + cbase;
    float4 yv = *(const float4*)(y + idx);
    float s1 = yv.x + yv.y + yv.z + yv.w;
    float s2 = yv.x * yv.x + yv.y * yv.y + yv.z * yv.z + yv.w * yv.w;
    float4 rv = *(const float4*)(r + idx);
    float4 kv = *(const float4*)(kadj + idx);
    float4 rkv = *(const float4*)(rk + cbase);
    float s3 = rv.x * kv.x * rkv.x + rv.y * kv.y * rkv.y +
               rv.z * kv.z * rkv.z + rv.w * kv.w * rkv.w;
#pragma unroll
    for (int off = 8; off > 0; off >>= 1) {
        s1 += __shfl_xor_sync(0xffffffffu, s1, off);
        s2 += __shfl_xor_sync(0xffffffffu, s2, off);
        s3 += __shfl_xor_sync(0xffffffffu, s3, off);
    }
    const float mu = s1 * (1.f / HS);
    const float var = s2 * (1.f / HS) - mu * mu;
    const float inv = rsqrtf(var + EPS_GN);
    float4 vv = *(const float4*)(v + idx);
    float4 gv = *(const float4*)(gg + idx);
    float4 lw = *(const float4*)(lnw + cbase);
    float4 lb = *(const float4*)(lnb + cbase);
    float4 res;
    res.x = (fmaf((yv.x - mu) * inv, lw.x, lb.x) + s3 * vv.x) * gv.x;
    res.y = (fmaf((yv.y - mu) * inv, lw.y, lb.y) + s3 * vv.y) * gv.y;
    res.z = (fmaf((yv.z - mu) * inv, lw.z, lb.z) + s3 * vv.z) * gv.z;
    res.w = (fmaf((yv.w - mu) * inv, lw.w, lb.w) + s3 * vv.w) * gv.w;
    *(float4*)(z + idx) = res;
}

// ---------------- launch ----------------
extern "C" void kernel_launch(void* const* d_in, const int* in_sizes, int n_in,
                              void* d_out, int out_size) {
    const float* x       = (const float*)d_in[0];
    const float* v_first = (const float*)d_in[1];
    const float* x_prev  = (const float*)d_in[2];
    const float* S0      = (const float*)d_in[3];
    const float* m_r = (const float*)d_in[4];
    const float* m_w = (const float*)d_in[5];
    const float* m_k = (const float*)d_in[6];
    const float* m_v = (const float*)d_in[7];
    const float* m_a = (const float*)d_in[8];
    const float* m_g = (const float*)d_in[9];

    const float *w0, *w1, *w2, *a0, *a1, *a2, *v0, *v1, *v2, *g1, *g2, *k_k, *k_a, *r_k;
    if (in_sizes[11] == C) {
        w0 = (const float*)d_in[10]; a0 = (const float*)d_in[11];
        v0 = (const float*)d_in[12]; k_k = (const float*)d_in[13];
        k_a = (const float*)d_in[14];
        w1 = (const float*)d_in[15]; w2 = (const float*)d_in[16];
        a1 = (const float*)d_in[17]; a2 = (const float*)d_in[18];
        v1 = (const float*)d_in[19]; v2 = (const float*)d_in[20];
        g1 = (const float*)d_in[21]; g2 = (const float*)d_in[22];
        r_k = (const float*)d_in[23];
    } else {
        w0 = (const float*)d_in[10]; w1 = (const float*)d_in[11];
        w2 = (const float*)d_in[12];
        a0 = (const float*)d_in[13]; a1 = (const float*)d_in[14];
        a2 = (const float*)d_in[15];
        v0 = (const float*)d_in[16]; v1 = (const float*)d_in[17];
        v2 = (const float*)d_in[18];
        g1 = (const float*)d_in[19]; g2 = (const float*)d_in[20];
        k_k = (const float*)d_in[21]; k_a = (const float*)d_in[22];
        r_k = (const float*)d_in[23];
    }

    const float* Wr = (const float*)d_in[24];
    const float* Wk = (const float*)d_in[25];
    const float* Wv = (const float*)d_in[26];
    const float* Wo = (const float*)d_in[27];
    const float* lnw = (const float*)d_in[28];
    const float* lnb = (const float*)d_in[29];
    const int*   cu  = (const int*)d_in[30];
    const int ncu = in_sizes[30];
    float* out = (float*)d_out;

    float* s = nullptr;
    cudaGetSymbolAddress((void**)&s, g_scratch);
    const size_t P = (size_t)T * C;
    float* xr = s;          float* xw = s + P;      float* xk = s + 2 * P;
    float* xv = s + 3 * P;  float* xa = s + 4 * P;  float* xg = s + 5 * P;
    float* rb = s + 6 * P;  float* kb = s + 7 * P;  float* vbuf = s + 8 * P;
    float* ewb = s + 9 * P; float* ab = s + 10 * P; float* gbuf = s + 11 * P;
    float* aab = s + 12 * P; float* bbb = s + 13 * P; float* kadj = s + 14 * P;
    float* yb = s + 15 * P;  float* zb = s + 16 * P;
    float* hw = s + 17 * P;
    float* ha = hw + (size_t)T * 64;
    float* hv = ha + (size_t)T * 64;
    float* hg = hv + (size_t)T * 32;

    k_shift_mix<<<T, 256>>>(x, x_prev, cu, ncu, m_r, m_w, m_k, m_v, m_a, m_g,
                            xr, xw, xk, xv, xa, xg);

    dim3 gemm_grid(C / 128, T / 128);
    k_gemm_nt<<<gemm_grid, 256>>>(xr, Wr, rb);
    k_gemm_nt<<<gemm_grid, 256>>>(xk, Wk, kb);
    k_gemm_nt<<<gemm_grid, 256>>>(xv, Wv, vbuf);

    k_stage1<64, 1><<<T / 32, 256>>>(xw, w1, hw);
    k_stage1<64, 0><<<T / 32, 256>>>(xa, a1, ha);
    k_stage1<32, 0><<<T / 32, 256>>>(xv, v1, hv);
    k_stage1<128, 2><<<T / 32, 256>>>(xg, g1, hg);

    dim3 s2grid(C / 128, T / 16);
    k_stage2<64, 0><<<s2grid, 128>>>(hw, w2, w0, nullptr, nullptr, ewb);
    k_stage2<64, 1><<<s2grid, 128>>>(ha, a2, a0, nullptr, nullptr, ab);
    k_stage2<32, 2><<<s2grid, 128>>>(hv, v2, v0, vbuf, v_first, vbuf);
    k_stage2<128, 3><<<s2grid, 128>>>(hg, g2, nullptr, nullptr, nullptr, gbuf);

    k_prep<<<T, 256>>>(kb, ab, k_k, k_a, aab, bbb, kadj);

    k_scan<<<dim3(NH, 8), 32>>>(rb, ewb, aab, bbb, kadj, vbuf, S0, yb);

    k_gn<<<T, 256>>>(yb, rb, kadj, vbuf, gbuf, r_k, lnw, lnb, zb);

    k_gemm_nt<<<gemm_grid, 256>>>(zb, Wo, out);
}

// round 7
// speedup vs baseline: 1.1548x; 1.1548x over previous
#include <cuda_runtime.h>
#include <math.h>

static const int T  = 2048;
static const int C  = 1024;
static const int NH = 16;
static const int HS = 64;
#define EPS_GN 0.00064f

typedef unsigned long long u64;

// ---------------- f32x2 packed helpers (sm_103a FFMA2 path) ----------------
__device__ __forceinline__ u64 fma2(u64 a, u64 b, u64 c) {
    u64 d; asm("fma.rn.f32x2 %0, %1, %2, %3;" : "=l"(d) : "l"(a), "l"(b), "l"(c)); return d;
}
__device__ __forceinline__ u64 mul2(u64 a, u64 b) {
    u64 d; asm("mul.rn.f32x2 %0, %1, %2;" : "=l"(d) : "l"(a), "l"(b)); return d;
}
__device__ __forceinline__ u64 add2(u64 a, u64 b) {
    u64 d; asm("add.rn.f32x2 %0, %1, %2;" : "=l"(d) : "l"(a), "l"(b)); return d;
}
__device__ __forceinline__ u64 pack2(float lo, float hi) {
    u64 d; asm("mov.b64 %0, {%1, %2};" : "=l"(d) : "f"(lo), "f"(hi)); return d;
}
__device__ __forceinline__ float2 unpack2(u64 v) {
    float2 r; asm("mov.b64 {%0, %1}, %2;" : "=f"(r.x), "=f"(r.y) : "l"(v)); return r;
}
__device__ __forceinline__ void cp16(unsigned s, const float* g) {
    asm volatile("cp.async.ca.shared.global [%0], [%1], 16;" :: "r"(s), "l"(g));
}

// ---------------- scratch ----------------
__device__ float g_scratch[(size_t)17 * 2048 * 1024 + (size_t)2048 * 288];

// ---------------- K1: token shift + 6-way mix ----------------
__global__ void k_shift_mix(const float* __restrict__ x, const float* __restrict__ x_prev,
                            const int* __restrict__ cu, int ncu,
                            const float* __restrict__ mr, const float* __restrict__ mw,
                            const float* __restrict__ mk, const float* __restrict__ mv,
                            const float* __restrict__ ma, const float* __restrict__ mg,
                            float* __restrict__ oxr, float* __restrict__ oxw,
                            float* __restrict__ oxk, float* __restrict__ oxv,
                            float* __restrict__ oxa, float* __restrict__ oxg) {
    const int t = blockIdx.x;
    int kind = (t == 0) ? 1 : 0;
    int prow = 0;
    for (int i = 0; i + 1 < ncu; i++) if (cu[i] == t) { kind = 2; prow = i; }
    const int c = threadIdx.x * 4;
    const size_t off = (size_t)t * C + c;
    float4 xc = *(const float4*)(x + off);
    float4 pv;
    if (kind == 0)      pv = *(const float4*)(x + off - C);
    else if (kind == 2) pv = *(const float4*)(x_prev + (size_t)prow * C + c);
    else                pv = make_float4(0.f, 0.f, 0.f, 0.f);
    float4 dx = make_float4(pv.x - xc.x, pv.y - xc.y, pv.z - xc.z, pv.w - xc.w);
#define MIXOUT(dst, m) { \
    float4 mm = *(const float4*)((m) + c); \
    float4 r_ = make_float4(fmaf(dx.x, mm.x, xc.x), fmaf(dx.y, mm.y, xc.y), \
                            fmaf(dx.z, mm.z, xc.z), fmaf(dx.w, mm.w, xc.w)); \
    *(float4*)((dst) + off) = r_; }
    MIXOUT(oxr, mr) MIXOUT(oxw, mw) MIXOUT(oxk, mk)
    MIXOUT(oxv, mv) MIXOUT(oxa, ma) MIXOUT(oxg, mg)
#undef MIXOUT
}

// ---------------- K2: fp32 NT GEMM via FFMA2, 128x128 tile, BK=16, double-buffered ----
__global__ void __launch_bounds__(256, 2) k_gemm_nt(const float* __restrict__ A,
                                                    const float* __restrict__ B,
                                                    float* __restrict__ Cg) {
    __shared__ float As[2][16][128];
    __shared__ float Bs[2][16][128];
    const int bm = blockIdx.y * 128;
    const int bn = blockIdx.x * 128;
    const int tid = threadIdx.x;
    const int tx = tid & 15, ty = tid >> 4;
    const int lr = tid >> 1;
    const int lk = (tid & 1) * 8;

    const float* Ap = A + (size_t)(bm + lr) * C + lk;
    const float* Bp = B + (size_t)(bn + lr) * C + lk;

    u64 acc[4][8];
#pragma unroll
    for (int p = 0; p < 4; p++)
#pragma unroll
        for (int j = 0; j < 8; j++) acc[p][j] = 0ull;

    float4 av0 = *(const float4*)Ap;
    float4 av1 = *(const float4*)(Ap + 4);
    float4 bv0 = *(const float4*)Bp;
    float4 bv1 = *(const float4*)(Bp + 4);

#define STS_TILE(bf) { \
    As[bf][lk+0][lr]=av0.x; As[bf][lk+1][lr]=av0.y; As[bf][lk+2][lr]=av0.z; As[bf][lk+3][lr]=av0.w; \
    As[bf][lk+4][lr]=av1.x; As[bf][lk+5][lr]=av1.y; As[bf][lk+6][lr]=av1.z; As[bf][lk+7][lr]=av1.w; \
    Bs[bf][lk+0][lr]=bv0.x; Bs[bf][lk+1][lr]=bv0.y; Bs[bf][lk+2][lr]=bv0.z; Bs[bf][lk+3][lr]=bv0.w; \
    Bs[bf][lk+4][lr]=bv1.x; Bs[bf][lk+5][lr]=bv1.y; Bs[bf][lk+6][lr]=bv1.z; Bs[bf][lk+7][lr]=bv1.w; }

    STS_TILE(0)
    __syncthreads();

    const int NIT = C / 16;
    for (int kt = 0; kt < NIT; kt++) {
        if (kt + 1 < NIT) {
            const float* Ap2 = Ap + (kt + 1) * 16;
            const float* Bp2 = Bp + (kt + 1) * 16;
            av0 = *(const float4*)Ap2; av1 = *(const float4*)(Ap2 + 4);
            bv0 = *(const float4*)Bp2; bv1 = *(const float4*)(Bp2 + 4);
        }
        const int buf = kt & 1;
#pragma unroll
        for (int kk = 0; kk < 16; kk++) {
            float4 a0 = *(const float4*)&As[buf][kk][ty * 8];
            float4 a1 = *(const float4*)&As[buf][kk][ty * 8 + 4];
            float4 b0 = *(const float4*)&Bs[buf][kk][tx * 8];
            float4 b1 = *(const float4*)&Bs[buf][kk][tx * 8 + 4];
            u64 ap[4];
            ap[0] = pack2(a0.x, a0.y); ap[1] = pack2(a0.z, a0.w);
            ap[2] = pack2(a1.x, a1.y); ap[3] = pack2(a1.z, a1.w);
            u64 bd[8];
            bd[0] = pack2(b0.x, b0.x); bd[1] = pack2(b0.y, b0.y);
            bd[2] = pack2(b0.z, b0.z); bd[3] = pack2(b0.w, b0.w);
            bd[4] = pack2(b1.x, b1.x); bd[5] = pack2(b1.y, b1.y);
            bd[6] = pack2(b1.z, b1.z); bd[7] = pack2(b1.w, b1.w);
#pragma unroll
            for (int p = 0; p < 4; p++)
#pragma unroll
                for (int j = 0; j < 8; j++)
                    acc[p][j] = fma2(ap[p], bd[j], acc[p][j]);
        }
        if (kt + 1 < NIT) {
            STS_TILE((kt + 1) & 1)
        }
        __syncthreads();
    }
#undef STS_TILE

#pragma unroll
    for (int p = 0; p < 4; p++) {
        float lo[8], hi[8];
#pragma unroll
        for (int j = 0; j < 8; j++) {
            float2 u = unpack2(acc[p][j]);
            lo[j] = u.x; hi[j] = u.y;
        }
        float* row0 = Cg + (size_t)(bm + ty * 8 + 2 * p) * C + bn + tx * 8;
        float* row1 = row0 + C;
        *(float4*)row0       = make_float4(lo[0], lo[1], lo[2], lo[3]);
        *(float4*)(row0 + 4) = make_float4(lo[4], lo[5], lo[6], lo[7]);
        *(float4*)row1       = make_float4(hi[0], hi[1], hi[2], hi[3]);
        *(float4*)(row1 + 4) = make_float4(hi[4], hi[5], hi[6], hi[7]);
    }
}

// ---------------- K3: stage-1 LoRA GEMM ----------------
template <int KO, int ACT>
__global__ void __launch_bounds__(256) k_stage1(const float* __restrict__ X,
                                                const float* __restrict__ W,
                                                float* __restrict__ out) {
    __shared__ float Xs[32][33];
    __shared__ float Ws[32][KO];
    const int t0 = blockIdx.x * 32;
    const int tid = threadIdx.x;
    const int j = tid % KO;
    const int tg = tid / KO;
    const int RPT = 256 / KO;
    const int NT = 32 / RPT;
    float acc[NT];
#pragma unroll
    for (int tt = 0; tt < NT; tt++) acc[tt] = 0.f;

    for (int cb = 0; cb < C; cb += 32) {
#pragma unroll
        for (int i = tid; i < 32 * 32; i += 256)
            Xs[i >> 5][i & 31] = X[(size_t)(t0 + (i >> 5)) * C + cb + (i & 31)];
#pragma unroll
        for (int i = tid; i < 32 * KO; i += 256)
            Ws[i / KO][i % KO] = W[(size_t)(cb + i / KO) * KO + (i % KO)];
        __syncthreads();
#pragma unroll
        for (int cc = 0; cc < 32; cc++) {
            float wv = Ws[cc][j];
#pragma unroll
            for (int tt = 0; tt < NT; tt++)
                acc[tt] = fmaf(Xs[tg * NT + tt][cc], wv, acc[tt]);
        }
        __syncthreads();
    }
#pragma unroll
    for (int tt = 0; tt < NT; tt++) {
        float val = acc[tt];
        if (ACT == 1) val = tanhf(val);
        else if (ACT == 2) val = 1.f / (1.f + expf(-val));
        out[(size_t)(t0 + tg * NT + tt) * KO + j] = val;
    }
}

// ---------------- K4: stage-2 LoRA GEMM + fused epilogue ----------------
template <int KI, int EPI>
__global__ void __launch_bounds__(128) k_stage2(const float* __restrict__ Hh,
                                                const float* __restrict__ W2,
                                                const float* __restrict__ bias,
                                                const float* __restrict__ e1,
                                                const float* __restrict__ e2,
                                                float* __restrict__ out) {
    __shared__ float Hs[16][KI];
    const int tb = blockIdx.y * 16;
    const int o = blockIdx.x * 128 + threadIdx.x;
    for (int i = threadIdx.x; i < 16 * KI; i += 128)
        Hs[i / KI][i % KI] = Hh[(size_t)(tb + i / KI) * KI + (i % KI)];
    __syncthreads();
    float acc[16];
#pragma unroll
    for (int t = 0; t < 16; t++) acc[t] = 0.f;
#pragma unroll 8
    for (int cdx = 0; cdx < KI; cdx++) {
        float wv = W2[(size_t)cdx * C + o];
#pragma unroll
        for (int t = 0; t < 16; t++)
            acc[t] = fmaf(Hs[t][cdx], wv, acc[t]);
    }
    float bv = (EPI == 3) ? 0.f : bias[o];
#pragma unroll
    for (int t = 0; t < 16; t++) {
        size_t idx = (size_t)(tb + t) * C + o;
        float zv = acc[t] + bv;
        float res;
        if (EPI == 0) {
            float xn = -zv;
            float sp = (xn > 20.f) ? xn : log1pf(expf(xn));
            res = expf(-expf(-sp - 0.5f));
        } else if (EPI == 1) {
            res = 1.f / (1.f + expf(-zv));
        } else if (EPI == 2) {
            float sg = 1.f / (1.f + expf(-zv));
            float vr = e1[idx];
            res = fmaf(e2[idx] - vr, sg, vr);
        } else {
            res = zv;
        }
        out[idx] = res;
    }
}

// ---------------- K5: scan-input prep ----------------
__global__ void k_prep(const float* __restrict__ kin, const float* __restrict__ ain,
                       const float* __restrict__ kkw, const float* __restrict__ kaw,
                       float* __restrict__ aab, float* __restrict__ bbb,
                       float* __restrict__ kadj) {
    const int t = blockIdx.x;
    const int tid = threadIdx.x;
    const int cbase = tid * 4;
    const size_t idx = (size_t)t * C + cbase;
    float4 kv = *(const float4*)(kin + idx);
    float4 av = *(const float4*)(ain + idx);
    float4 kw = *(const float4*)(kkw + cbase);
    float4 aw = *(const float4*)(kaw + cbase);
    float4 kk = make_float4(kv.x * kw.x, kv.y * kw.y, kv.z * kw.z, kv.w * kw.w);
    float ss = kk.x * kk.x + kk.y * kk.y + kk.z * kk.z + kk.w * kk.w;
#pragma unroll
    for (int off = 8; off > 0; off >>= 1)
        ss += __shfl_xor_sync(0xffffffffu, ss, off);
    float inv = 1.f / fmaxf(sqrtf(ss), 1e-12f);
    float4 kn = make_float4(kk.x * inv, kk.y * inv, kk.z * inv, kk.w * inv);
    *(float4*)(aab + idx) = make_float4(-kn.x, -kn.y, -kn.z, -kn.w);
    *(float4*)(bbb + idx) = make_float4(kn.x * av.x, kn.y * av.y, kn.z * av.z, kn.w * av.w);
    *(float4*)(kadj + idx) = make_float4(
        kv.x * fmaf(av.x - 1.f, aw.x, 1.f),
        kv.y * fmaf(av.y - 1.f, aw.y, 1.f),
        kv.z * fmaf(av.z - 1.f, aw.z, 1.f),
        kv.w * fmaf(av.w - 1.f, aw.w, 1.f));
}

// ---------------- K6: RWKV-7 serial scan (chunked cp.async groups + FFMA2) ------------
union U16 { float f[16]; u64 u[8]; float4 v[4]; };

#define RING_SLOTS 16
#define CHUNK 4

__global__ void __launch_bounds__(32) k_scan(const float* __restrict__ rb,
                                             const float* __restrict__ ewb,
                                             const float* __restrict__ aab,
                                             const float* __restrict__ bbb,
                                             const float* __restrict__ kb,
                                             const float* __restrict__ vb,
                                             const float* __restrict__ S0,
                                             float* __restrict__ y) {
    __shared__ float ring[RING_SLOTS][6 * HS];
    const int h  = blockIdx.x;
    const int vg = blockIdx.y;
    const int tid = threadIdx.x;
    const int jg = tid & 3;
    const int vr = tid >> 2;
    const int vrow = vg * 8 + vr;
    const int jb = jg * 16;

    U16 S;
#pragma unroll
    for (int q = 0; q < 4; q++)
        S.v[q] = *(const float4*)(S0 + (size_t)h * HS * HS + (size_t)vrow * HS + jb + q * 4);

    const int off16 = (tid & 15) << 2;
    const int arr0 = tid >> 4;
    const int arr1 = arr0 + 2;
    const int arr2 = arr0 + 4;
    const float* s0 = (arr0 == 0 ? rb  : ewb) + (size_t)h * HS + off16;
    const float* s1 = (arr1 == 2 ? aab : bbb) + (size_t)h * HS + off16;
    const float* s2 = (arr2 == 4 ? kb  : vb ) + (size_t)h * HS + off16;
    unsigned base_u = (unsigned)__cvta_generic_to_shared(&ring[0][0]);
    const unsigned d0 = base_u + (unsigned)(arr0 * HS + off16) * 4u;
    const unsigned d1 = base_u + (unsigned)(arr1 * HS + off16) * 4u;
    const unsigned d2 = base_u + (unsigned)(arr2 * HS + off16) * 4u;

// one commit group per CHUNK of 4 steps; indices clamped so every chunk issues
#define ISSUE_CHUNK(cb) { \
    _Pragma("unroll") \
    for (int s_ = 0; s_ < CHUNK; s_++) { \
        int st_ = (cb) * CHUNK + s_; \
        int slot_ = st_ & (RING_SLOTS - 1); \
        if (st_ >= T) st_ = T - 1; \
        size_t so_ = (size_t)st_ * C; \
        unsigned sb_ = (unsigned)slot_ * (6 * HS * 4); \
        cp16(d0 + sb_, s0 + so_); \
        cp16(d1 + sb_, s1 + so_); \
        cp16(d2 + sb_, s2 + so_); \
    } \
    asm volatile("cp.async.commit_group;"); }

    ISSUE_CHUNK(0)
    ISSUE_CHUNK(1)
    ISSUE_CHUNK(2)

    float o_l = 0.f, os1 = 0.f, os2 = 0.f, os3 = 0.f;
    const size_t ybase = (size_t)h * HS + vrow;
    const int NCH = T / CHUNK;

    for (int c = 0; c < NCH; c++) {
        asm volatile("cp.async.wait_group 2;");   // chunk c's group complete
        __syncwarp();

#pragma unroll
        for (int s = 0; s < CHUNK; s++) {
            const int t = c * CHUNK + s;
            if (t > 0 && jg == 0)
                y[(size_t)(t - 1) * C + ybase] = (o_l + os1) + (os2 + os3);

            const float* sp = &ring[t & (RING_SLOTS - 1)][0];
            U16 Rv, Ev, Av, Bv, Kv;
#pragma unroll
            for (int q = 0; q < 4; q++) {
                Rv.v[q] = *(const float4*)&sp[0 * HS + jb + q * 4];
                Ev.v[q] = *(const float4*)&sp[1 * HS + jb + q * 4];
                Av.v[q] = *(const float4*)&sp[2 * HS + jb + q * 4];
                Bv.v[q] = *(const float4*)&sp[3 * HS + jb + q * 4];
                Kv.v[q] = *(const float4*)&sp[4 * HS + jb + q * 4];
            }
            const float vt = sp[5 * HS + vrow];

            // sa partial via FFMA2
            u64 sacc0 = mul2(S.u[0], Av.u[0]);
            u64 sacc1 = mul2(S.u[1], Av.u[1]);
#pragma unroll
            for (int q = 2; q < 8; q += 2) {
                sacc0 = fma2(S.u[q],     Av.u[q],     sacc0);
                sacc1 = fma2(S.u[q + 1], Av.u[q + 1], sacc1);
            }
            float2 sp2 = unpack2(add2(sacc0, sacc1));
            float sal = sp2.x + sp2.y;
            float sA = __shfl_xor_sync(0xffffffffu, sal, 1);
            float sB = __shfl_xor_sync(0xffffffffu, sal, 2);
            float sC = __shfl_xor_sync(0xffffffffu, sal, 3);

            // overlap shfl latency: pre = S*ew + vt*k
            u64 vt2 = pack2(vt, vt);
            u64 pre[8];
#pragma unroll
            for (int q = 0; q < 8; q++)
                pre[q] = fma2(S.u[q], Ev.u[q], mul2(vt2, Kv.u[q]));

            float sa = (sal + sA) + (sB + sC);
            u64 sa2 = pack2(sa, sa);

            u64 oa0 = 0ull, oa1 = 0ull;
#pragma unroll
            for (int q = 0; q < 8; q += 2) {
                S.u[q]     = fma2(sa2, Bv.u[q],     pre[q]);
                S.u[q + 1] = fma2(sa2, Bv.u[q + 1], pre[q + 1]);
                oa0 = fma2(S.u[q],     Rv.u[q],     oa0);
                oa1 = fma2(S.u[q + 1], Rv.u[q + 1], oa1);
            }
            float2 op2 = unpack2(add2(oa0, oa1));
            o_l = op2.x + op2.y;
            os1 = __shfl_xor_sync(0xffffffffu, o_l, 1);
            os2 = __shfl_xor_sync(0xffffffffu, o_l, 2);
            os3 = __shfl_xor_sync(0xffffffffu, o_l, 3);
        }

        ISSUE_CHUNK(c + 3)
    }
    if (jg == 0)
        y[(size_t)(T - 1) * C + ybase] = (o_l + os1) + (os2 + os3);
#undef ISSUE_CHUNK
}

// ---------------- K7: GroupNorm + bonus + gate ----------------
__global__ void k_gn(const float* __restrict__ y, const float* __restrict__ r,
                     const float* __restrict__ kadj, const float* __restrict__ v,
                     const float* __restrict__ gg, const float* __restrict__ rk,
                     const float* __restrict__ lnw, const float* __restrict__ lnb,
                     float* __restrict__ z) {
    const int t = blockIdx.x;
    const int tid = threadIdx.x;
    const int cbase = tid * 4;
    const size_t idx = (size_t)t * C + cbase;
    float4 yv = *(const float4*)(y + idx);
    float s1 = yv.x + yv.y + yv.z + yv.w;
    float s2 = yv.x * yv.x + yv.y * yv.y + yv.z * yv.z + yv.w * yv.w;
    float4 rv = *(const float4*)(r + idx);
    float4 kv = *(const float4*)(kadj + idx);
    float4 rkv = *(const float4*)(rk + cbase);
    float s3 = rv.x * kv.x * rkv.x + rv.y * kv.y * rkv.y +
               rv.z * kv.z * rkv.z + rv.w * kv.w * rkv.w;
#pragma unroll
    for (int off = 8; off > 0; off >>= 1) {
        s1 += __shfl_xor_sync(0xffffffffu, s1, off);
        s2 += __shfl_xor_sync(0xffffffffu, s2, off);
        s3 += __shfl_xor_sync(0xffffffffu, s3, off);
    }
    const float mu = s1 * (1.f / HS);
    const float var = s2 * (1.f / HS) - mu * mu;
    const float inv = rsqrtf(var + EPS_GN);
    float4 vv = *(const float4*)(v + idx);
    float4 gv = *(const float4*)(gg + idx);
    float4 lw = *(const float4*)(lnw + cbase);
    float4 lb = *(const float4*)(lnb + cbase);
    float4 res;
    res.x = (fmaf((yv.x - mu) * inv, lw.x, lb.x) + s3 * vv.x) * gv.x;
    res.y = (fmaf((yv.y - mu) * inv, lw.y, lb.y) + s3 * vv.y) * gv.y;
    res.z = (fmaf((yv.z - mu) * inv, lw.z, lb.z) + s3 * vv.z) * gv.z;
    res.w = (fmaf((yv.w - mu) * inv, lw.w, lb.w) + s3 * vv.w) * gv.w;
    *(float4*)(z + idx) = res;
}

// ---------------- launch ----------------
extern "C" void kernel_launch(void* const* d_in, const int* in_sizes, int n_in,
                              void* d_out, int out_size) {
    const float* x       = (const float*)d_in[0];
    const float* v_first = (const float*)d_in[1];
    const float* x_prev  = (const float*)d_in[2];
    const float* S0      = (const float*)d_in[3];
    const float* m_r = (const float*)d_in[4];
    const float* m_w = (const float*)d_in[5];
    const float* m_k = (const float*)d_in[6];
    const float* m_v = (const float*)d_in[7];
    const float* m_a = (const float*)d_in[8];
    const float* m_g = (const float*)d_in[9];

    const float *w0, *w1, *w2, *a0, *a1, *a2, *v0, *v1, *v2, *g1, *g2, *k_k, *k_a, *r_k;
    if (in_sizes[11] == C) {
        w0 = (const float*)d_in[10]; a0 = (const float*)d_in[11];
        v0 = (const float*)d_in[12]; k_k = (const float*)d_in[13];
        k_a = (const float*)d_in[14];
        w1 = (const float*)d_in[15]; w2 = (const float*)d_in[16];
        a1 = (const float*)d_in[17]; a2 = (const float*)d_in[18];
        v1 = (const float*)d_in[19]; v2 = (const float*)d_in[20];
        g1 = (const float*)d_in[21]; g2 = (const float*)d_in[22];
        r_k = (const float*)d_in[23];
    } else {
        w0 = (const float*)d_in[10]; w1 = (const float*)d_in[11];
        w2 = (const float*)d_in[12];
        a0 = (const float*)d_in[13]; a1 = (const float*)d_in[14];
        a2 = (const float*)d_in[15];
        v0 = (const float*)d_in[16]; v1 = (const float*)d_in[17];
        v2 = (const float*)d_in[18];
        g1 = (const float*)d_in[19]; g2 = (const float*)d_in[20];
        k_k = (const float*)d_in[21]; k_a = (const float*)d_in[22];
        r_k = (const float*)d_in[23];
    }

    const float* Wr = (const float*)d_in[24];
    const float* Wk = (const float*)d_in[25];
    const float* Wv = (const float*)d_in[26];
    const float* Wo = (const float*)d_in[27];
    const float* lnw = (const float*)d_in[28];
    const float* lnb = (const float*)d_in[29];
    const int*   cu  = (const int*)d_in[30];
    const int ncu = in_sizes[30];
    float* out = (float*)d_out;

    float* s = nullptr;
    cudaGetSymbolAddress((void**)&s, g_scratch);
    const size_t P = (size_t)T * C;
    float* xr = s;          float* xw = s + P;      float* xk = s + 2 * P;
    float* xv = s + 3 * P;  float* xa = s + 4 * P;  float* xg = s + 5 * P;
    float* rb = s + 6 * P;  float* kb = s + 7 * P;  float* vbuf = s + 8 * P;
    float* ewb = s + 9 * P; float* ab = s + 10 * P; float* gbuf = s + 11 * P;
    float* aab = s + 12 * P; float* bbb = s + 13 * P; float* kadj = s + 14 * P;
    float* yb = s + 15 * P;  float* zb = s + 16 * P;
    float* hw = s + 17 * P;
    float* ha = hw + (size_t)T * 64;
    float* hv = ha + (size_t)T * 64;
    float* hg = hv + (size_t)T * 32;

    k_shift_mix<<<T, 256>>>(x, x_prev, cu, ncu, m_r, m_w, m_k, m_v, m_a, m_g,
                            xr, xw, xk, xv, xa, xg);

    dim3 gemm_grid(C / 128, T / 128);
    k_gemm_nt<<<gemm_grid, 256>>>(xr, Wr, rb);
    k_gemm_nt<<<gemm_grid, 256>>>(xk, Wk, kb);
    k_gemm_nt<<<gemm_grid, 256>>>(xv, Wv, vbuf);

    k_stage1<64, 1><<<T / 32, 256>>>(xw, w1, hw);
    k_stage1<64, 0><<<T / 32, 256>>>(xa, a1, ha);
    k_stage1<32, 0><<<T / 32, 256>>>(xv, v1, hv);
    k_stage1<128, 2><<<T / 32, 256>>>(xg, g1, hg);

    dim3 s2grid(C / 128, T / 16);
    k_stage2<64, 0><<<s2grid, 128>>>(hw, w2, w0, nullptr, nullptr, ewb);
    k_stage2<64, 1><<<s2grid, 128>>>(ha, a2, a0, nullptr, nullptr, ab);
    k_stage2<32, 2><<<s2grid, 128>>>(hv, v2, v0, vbuf, v_first, vbuf);
    k_stage2<128, 3><<<s2grid, 128>>>(hg, g2, nullptr, nullptr, nullptr, gbuf);

    k_prep<<<T, 256>>>(kb, ab, k_k, k_a, aab, bbb, kadj);

    k_scan<<<dim3(NH, 8), 32>>>(rb, ewb, aab, bbb, kadj, vbuf, S0, yb);

    k_gn<<<T, 256>>>(yb, rb, kadj, vbuf, gbuf, r_k, lnw, lnb, zb);

    k_gemm_nt<<<gemm_grid, 256>>>(zb, Wo, out);
}

// round 9
// speedup vs baseline: 1.4139x; 1.2244x over previous
#include <cuda_runtime.h>
#include <math.h>

static const int T  = 2048;
static const int C  = 1024;
static const int NH = 16;
static const int HS = 64;
#define EPS_GN 0.00064f

typedef unsigned long long u64;
typedef unsigned int u32;

// ---------------- f32x2 packed helpers (sm_103a FFMA2 path) ----------------
__device__ __forceinline__ u64 fma2(u64 a, u64 b, u64 c) {
    u64 d; asm("fma.rn.f32x2 %0, %1, %2, %3;" : "=l"(d) : "l"(a), "l"(b), "l"(c)); return d;
}
__device__ __forceinline__ u64 mul2(u64 a, u64 b) {
    u64 d; asm("mul.rn.f32x2 %0, %1, %2;" : "=l"(d) : "l"(a), "l"(b)); return d;
}
__device__ __forceinline__ u64 add2(u64 a, u64 b) {
    u64 d; asm("add.rn.f32x2 %0, %1, %2;" : "=l"(d) : "l"(a), "l"(b)); return d;
}
__device__ __forceinline__ u64 pack2(float lo, float hi) {
    u64 d; asm("mov.b64 %0, {%1, %2};" : "=l"(d) : "f"(lo), "f"(hi)); return d;
}
__device__ __forceinline__ float2 unpack2(u64 v) {
    float2 r; asm("mov.b64 {%0, %1}, %2;" : "=f"(r.x), "=f"(r.y) : "l"(v)); return r;
}
__device__ __forceinline__ void cp16(unsigned s, const float* g) {
    asm volatile("cp.async.ca.shared.global [%0], [%1], 16;" :: "r"(s), "l"(g));
}

// ---------------- scratch ----------------
__device__ float g_scratch[(size_t)17 * 2048 * 1024 + (size_t)2048 * 288];

// ---------------- K1: token shift + 6-way mix ----------------
__global__ void k_shift_mix(const float* __restrict__ x, const float* __restrict__ x_prev,
                            const int* __restrict__ cu, int ncu,
                            const float* __restrict__ mr, const float* __restrict__ mw,
                            const float* __restrict__ mk, const float* __restrict__ mv,
                            const float* __restrict__ ma, const float* __restrict__ mg,
                            float* __restrict__ oxr, float* __restrict__ oxw,
                            float* __restrict__ oxk, float* __restrict__ oxv,
                            float* __restrict__ oxa, float* __restrict__ oxg) {
    const int t = blockIdx.x;
    int kind = (t == 0) ? 1 : 0;
    int prow = 0;
    for (int i = 0; i + 1 < ncu; i++) if (cu[i] == t) { kind = 2; prow = i; }
    const int c = threadIdx.x * 4;
    const size_t off = (size_t)t * C + c;
    float4 xc = *(const float4*)(x + off);
    float4 pv;
    if (kind == 0)      pv = *(const float4*)(x + off - C);
    else if (kind == 2) pv = *(const float4*)(x_prev + (size_t)prow * C + c);
    else                pv = make_float4(0.f, 0.f, 0.f, 0.f);
    float4 dx = make_float4(pv.x - xc.x, pv.y - xc.y, pv.z - xc.z, pv.w - xc.w);
#define MIXOUT(dst, m) { \
    float4 mm = *(const float4*)((m) + c); \
    float4 r_ = make_float4(fmaf(dx.x, mm.x, xc.x), fmaf(dx.y, mm.y, xc.y), \
                            fmaf(dx.z, mm.z, xc.z), fmaf(dx.w, mm.w, xc.w)); \
    *(float4*)((dst) + off) = r_; }
    MIXOUT(oxr, mr) MIXOUT(oxw, mw) MIXOUT(oxk, mk)
    MIXOUT(oxv, mv) MIXOUT(oxa, ma) MIXOUT(oxg, mg)
#undef MIXOUT
}

// ---------------- K2: bf16x3 tensor-core NT GEMM via mma.sync (HMMA path) -------------
// Cg[m][n] = sum_k A[m][k]*B[n][k]. fp32 = hi(bf16 trunc, exact) + lo(bf16 rounded).
// D += Ah*Bh + Ah*Bl + Al*Bh  (fp32 accum). rel err ~1e-5.
// 128x128 CTA tile, 256 thr = 8 warps (2M x 4N), warp tile 64x32, K chunk 32.
// smem row stride 18 u32 (16 data + 2 pad) -> conflict-free fragment LDS.
#define SROW 18

#define MMA_BF16(ac, av, bv) \
    asm volatile("mma.sync.aligned.m16n8k16.row.col.f32.bf16.bf16.f32 " \
        "{%0,%1,%2,%3},{%4,%5,%6,%7},{%8,%9},{%0,%1,%2,%3};" \
        : "+f"((ac)[0]), "+f"((ac)[1]), "+f"((ac)[2]), "+f"((ac)[3]) \
        : "r"((av)[0]), "r"((av)[1]), "r"((av)[2]), "r"((av)[3]), \
          "r"((bv)[0]), "r"((bv)[1]))

__global__ void __launch_bounds__(256) k_gemm_mma(const float* __restrict__ A,
                                                  const float* __restrict__ B,
                                                  float* __restrict__ Cg) {
    __shared__ u32 Ah[128 * SROW];
    __shared__ u32 Al[128 * SROW];
    __shared__ u32 Bh[128 * SROW];
    __shared__ u32 Bl[128 * SROW];

    const int bm = blockIdx.y * 128;
    const int bn = blockIdx.x * 128;
    const int tid = threadIdx.x;
    const int wid = tid >> 5;
    const int lane = tid & 31;
    const int wm = (wid & 1) * 64;    // warp M offset
    const int wn = (wid >> 1) * 32;   // warp N offset
    const int g = lane >> 2;          // 0..7
    const int tg = lane & 3;          // 0..3

    float acc[4][4][4];
#pragma unroll
    for (int mt = 0; mt < 4; mt++)
#pragma unroll
        for (int nt = 0; nt < 4; nt++)
#pragma unroll
            for (int q = 0; q < 4; q++) acc[mt][nt][q] = 0.f;

    float2 aPre[8], bPre[8];
#define LDG_CHUNK(cc) { \
    _Pragma("unroll") \
    for (int i = 0; i < 8; i++) { \
        const int p = i * 256 + tid; \
        const int row = p >> 4; \
        const int kk = (p & 15) * 2; \
        aPre[i] = *(const float2*)(A + (size_t)(bm + row) * C + (cc) * 32 + kk); \
        bPre[i] = *(const float2*)(B + (size_t)(bn + row) * C + (cc) * 32 + kk); \
    } }

#define SPLIT_STORE(f2, Hbuf, Lbuf, w) { \
    u32 bx_ = __float_as_uint((f2).x), by_ = __float_as_uint((f2).y); \
    u32 hx_ = bx_ & 0xFFFF0000u, hy_ = by_ & 0xFFFF0000u; \
    (Hbuf)[w] = (hx_ >> 16) | hy_; \
    float lx_ = (f2).x - __uint_as_float(hx_); \
    float ly_ = (f2).y - __uint_as_float(hy_); \
    u32 lp_; \
    asm("cvt.rn.satfinite.bf16x2.f32 %0, %1, %2;" : "=r"(lp_) : "f"(ly_), "f"(lx_)); \
    (Lbuf)[w] = lp_; }

#define STS_CHUNK() { \
    _Pragma("unroll") \
    for (int i = 0; i < 8; i++) { \
        const int p = i * 256 + tid; \
        const int row = p >> 4; \
        const int colw = p & 15; \
        const u32 w_ = (u32)(row * SROW + colw); \
        SPLIT_STORE(aPre[i], Ah, Al, w_) \
        SPLIT_STORE(bPre[i], Bh, Bl, w_) \
    } }

    LDG_CHUNK(0)

    const int NCHUNK = C / 32;
    for (int c = 0; c < NCHUNK; c++) {
        STS_CHUNK()
        __syncthreads();
        if (c + 1 < NCHUNK) LDG_CHUNK(c + 1)

#pragma unroll
        for (int k16 = 0; k16 < 2; k16++) {
            const int colb = k16 * 8 + tg;

            u32 aH[4][4];
#pragma unroll
            for (int mt = 0; mt < 4; mt++) {
                const int base = (wm + mt * 16 + g) * SROW + colb;
                aH[mt][0] = Ah[base];
                aH[mt][1] = Ah[base + 8 * SROW];
                aH[mt][2] = Ah[base + 4];
                aH[mt][3] = Ah[base + 8 * SROW + 4];
            }
            u32 bH[4][2];
#pragma unroll
            for (int nt = 0; nt < 4; nt++) {
                const int base = (wn + nt * 8 + g) * SROW + colb;
                bH[nt][0] = Bh[base];
                bH[nt][1] = Bh[base + 4];
            }
            // hi * hi
#pragma unroll
            for (int mt = 0; mt < 4; mt++)
#pragma unroll
                for (int nt = 0; nt < 4; nt++)
                    MMA_BF16(acc[mt][nt], aH[mt], bH[nt]);

            // hi * lo (reuse aH)
            u32 bL[4][2];
#pragma unroll
            for (int nt = 0; nt < 4; nt++) {
                const int base = (wn + nt * 8 + g) * SROW + colb;
                bL[nt][0] = Bl[base];
                bL[nt][1] = Bl[base + 4];
            }
#pragma unroll
            for (int mt = 0; mt < 4; mt++)
#pragma unroll
                for (int nt = 0; nt < 4; nt++)
                    MMA_BF16(acc[mt][nt], aH[mt], bL[nt]);

            // lo * hi (reuse bH)
            u32 aL[4][4];
#pragma unroll
            for (int mt = 0; mt < 4; mt++) {
                const int base = (wm + mt * 16 + g) * SROW + colb;
                aL[mt][0] = Al[base];
                aL[mt][1] = Al[base + 8 * SROW];
                aL[mt][2] = Al[base + 4];
                aL[mt][3] = Al[base + 8 * SROW + 4];
            }
#pragma unroll
            for (int mt = 0; mt < 4; mt++)
#pragma unroll
                for (int nt = 0; nt < 4; nt++)
                    MMA_BF16(acc[mt][nt], aL[mt], bH[nt]);
        }
        __syncthreads();
    }

#pragma unroll
    for (int mt = 0; mt < 4; mt++) {
#pragma unroll
        for (int nt = 0; nt < 4; nt++) {
            const int row = bm + wm + mt * 16 + g;
            const int col = bn + wn + nt * 8 + tg * 2;
            *(float2*)(Cg + (size_t)row * C + col) =
                make_float2(acc[mt][nt][0], acc[mt][nt][1]);
            *(float2*)(Cg + (size_t)(row + 8) * C + col) =
                make_float2(acc[mt][nt][2], acc[mt][nt][3]);
        }
    }
#undef LDG_CHUNK
#undef STS_CHUNK
#undef SPLIT_STORE
}

// ---------------- K3: stage-1 LoRA GEMM ----------------
template <int KO, int ACT>
__global__ void __launch_bounds__(256) k_stage1(const float* __restrict__ X,
                                                const float* __restrict__ W,
                                                float* __restrict__ out) {
    __shared__ float Xs[32][33];
    __shared__ float Ws[32][KO];
    const int t0 = blockIdx.x * 32;
    const int tid = threadIdx.x;
    const int j = tid % KO;
    const int tg = tid / KO;
    const int RPT = 256 / KO;
    const int NT = 32 / RPT;
    float acc[NT];
#pragma unroll
    for (int tt = 0; tt < NT; tt++) acc[tt] = 0.f;

    for (int cb = 0; cb < C; cb += 32) {
#pragma unroll
        for (int i = tid; i < 32 * 32; i += 256)
            Xs[i >> 5][i & 31] = X[(size_t)(t0 + (i >> 5)) * C + cb + (i & 31)];
#pragma unroll
        for (int i = tid; i < 32 * KO; i += 256)
            Ws[i / KO][i % KO] = W[(size_t)(cb + i / KO) * KO + (i % KO)];
        __syncthreads();
#pragma unroll
        for (int cc = 0; cc < 32; cc++) {
            float wv = Ws[cc][j];
#pragma unroll
            for (int tt = 0; tt < NT; tt++)
                acc[tt] = fmaf(Xs[tg * NT + tt][cc], wv, acc[tt]);
        }
        __syncthreads();
    }
#pragma unroll
    for (int tt = 0; tt < NT; tt++) {
        float val = acc[tt];
        if (ACT == 1) val = tanhf(val);
        else if (ACT == 2) val = 1.f / (1.f + expf(-val));
        out[(size_t)(t0 + tg * NT + tt) * KO + j] = val;
    }
}

// ---------------- K4: stage-2 LoRA GEMM + fused epilogue ----------------
template <int KI, int EPI>
__global__ void __launch_bounds__(128) k_stage2(const float* __restrict__ Hh,
                                                const float* __restrict__ W2,
                                                const float* __restrict__ bias,
                                                const float* __restrict__ e1,
                                                const float* __restrict__ e2,
                                                float* __restrict__ out) {
    __shared__ float Hs[16][KI];
    const int tb = blockIdx.y * 16;
    const int o = blockIdx.x * 128 + threadIdx.x;
    for (int i = threadIdx.x; i < 16 * KI; i += 128)
        Hs[i / KI][i % KI] = Hh[(size_t)(tb + i / KI) * KI + (i % KI)];
    __syncthreads();
    float acc[16];
#pragma unroll
    for (int t = 0; t < 16; t++) acc[t] = 0.f;
#pragma unroll 8
    for (int cdx = 0; cdx < KI; cdx++) {
        float wv = W2[(size_t)cdx * C + o];
#pragma unroll
        for (int t = 0; t < 16; t++)
            acc[t] = fmaf(Hs[t][cdx], wv, acc[t]);
    }
    float bv = (EPI == 3) ? 0.f : bias[o];
#pragma unroll
    for (int t = 0; t < 16; t++) {
        size_t idx = (size_t)(tb + t) * C + o;
        float zv = acc[t] + bv;
        float res;
        if (EPI == 0) {
            float xn = -zv;
            float sp = (xn > 20.f) ? xn : log1pf(expf(xn));
            res = expf(-expf(-sp - 0.5f));
        } else if (EPI == 1) {
            res = 1.f / (1.f + expf(-zv));
        } else if (EPI == 2) {
            float sg = 1.f / (1.f + expf(-zv));
            float vr = e1[idx];
            res = fmaf(e2[idx] - vr, sg, vr);
        } else {
            res = zv;
        }
        out[idx] = res;
    }
}

// ---------------- K5: scan-input prep ----------------
__global__ void k_prep(const float* __restrict__ kin, const float* __restrict__ ain,
                       const float* __restrict__ kkw, const float* __restrict__ kaw,
                       float* __restrict__ aab, float* __restrict__ bbb,
                       float* __restrict__ kadj) {
    const int t = blockIdx.x;
    const int tid = threadIdx.x;
    const int cbase = tid * 4;
    const size_t idx = (size_t)t * C + cbase;
    float4 kv = *(const float4*)(kin + idx);
    float4 av = *(const float4*)(ain + idx);
    float4 kw = *(const float4*)(kkw + cbase);
    float4 aw = *(const float4*)(kaw + cbase);
    float4 kk = make_float4(kv.x * kw.x, kv.y * kw.y, kv.z * kw.z, kv.w * kw.w);
    float ss = kk.x * kk.x + kk.y * kk.y + kk.z * kk.z + kk.w * kk.w;
#pragma unroll
    for (int off = 8; off > 0; off >>= 1)
        ss += __shfl_xor_sync(0xffffffffu, ss, off);
    float inv = 1.f / fmaxf(sqrtf(ss), 1e-12f);
    float4 kn = make_float4(kk.x * inv, kk.y * inv, kk.z * inv, kk.w * inv);
    *(float4*)(aab + idx) = make_float4(-kn.x, -kn.y, -kn.z, -kn.w);
    *(float4*)(bbb + idx) = make_float4(kn.x * av.x, kn.y * av.y, kn.z * av.z, kn.w * av.w);
    *(float4*)(kadj + idx) = make_float4(
        kv.x * fmaf(av.x - 1.f, aw.x, 1.f),
        kv.y * fmaf(av.y - 1.f, aw.y, 1.f),
        kv.z * fmaf(av.z - 1.f, aw.z, 1.f),
        kv.w * fmaf(av.w - 1.f, aw.w, 1.f));
}

// ---------------- K6: RWKV-7 serial scan (chunked cp.async groups + FFMA2) ------------
union U16 { float f[16]; u64 u[8]; float4 v[4]; };

#define RING_SLOTS 16
#define CHUNK 4

__global__ void __launch_bounds__(32) k_scan(const float* __restrict__ rb,
                                             const float* __restrict__ ewb,
                                             const float* __restrict__ aab,
                                             const float* __restrict__ bbb,
                                             const float* __restrict__ kb,
                                             const float* __restrict__ vb,
                                             const float* __restrict__ S0,
                                             float* __restrict__ y) {
    __shared__ float ring[RING_SLOTS][6 * HS];
    const int h  = blockIdx.x;
    const int vg = blockIdx.y;
    const int tid = threadIdx.x;
    const int jg = tid & 3;
    const int vr = tid >> 2;
    const int vrow = vg * 8 + vr;
    const int jb = jg * 16;

    U16 S;
#pragma unroll
    for (int q = 0; q < 4; q++)
        S.v[q] = *(const float4*)(S0 + (size_t)h * HS * HS + (size_t)vrow * HS + jb + q * 4);

    const int off16 = (tid & 15) << 2;
    const int arr0 = tid >> 4;
    const int arr1 = arr0 + 2;
    const int arr2 = arr0 + 4;
    const float* s0 = (arr0 == 0 ? rb  : ewb) + (size_t)h * HS + off16;
    const float* s1 = (arr1 == 2 ? aab : bbb) + (size_t)h * HS + off16;
    const float* s2 = (arr2 == 4 ? kb  : vb ) + (size_t)h * HS + off16;
    unsigned base_u = (unsigned)__cvta_generic_to_shared(&ring[0][0]);
    const unsigned d0 = base_u + (unsigned)(arr0 * HS + off16) * 4u;
    const unsigned d1 = base_u + (unsigned)(arr1 * HS + off16) * 4u;
    const unsigned d2 = base_u + (unsigned)(arr2 * HS + off16) * 4u;

#define ISSUE_CHUNK(cb) { \
    _Pragma("unroll") \
    for (int s_ = 0; s_ < CHUNK; s_++) { \
        int st_ = (cb) * CHUNK + s_; \
        int slot_ = st_ & (RING_SLOTS - 1); \
        if (st_ >= T) st_ = T - 1; \
        size_t so_ = (size_t)st_ * C; \
        unsigned sb_ = (unsigned)slot_ * (6 * HS * 4); \
        cp16(d0 + sb_, s0 + so_); \
        cp16(d1 + sb_, s1 + so_); \
        cp16(d2 + sb_, s2 + so_); \
    } \
    asm volatile("cp.async.commit_group;"); }

    ISSUE_CHUNK(0)
    ISSUE_CHUNK(1)
    ISSUE_CHUNK(2)

    float o_l = 0.f, os1 = 0.f, os2 = 0.f, os3 = 0.f;
    const size_t ybase = (size_t)h * HS + vrow;
    const int NCH = T / CHUNK;

    for (int c = 0; c < NCH; c++) {
        asm volatile("cp.async.wait_group 2;");
        __syncwarp();

#pragma unroll
        for (int s = 0; s < CHUNK; s++) {
            const int t = c * CHUNK + s;
            if (t > 0 && jg == 0)
                y[(size_t)(t - 1) * C + ybase] = (o_l + os1) + (os2 + os3);

            const float* sp = &ring[t & (RING_SLOTS - 1)][0];
            U16 Rv, Ev, Av, Bv, Kv;
#pragma unroll
            for (int q = 0; q < 4; q++) {
                Rv.v[q] = *(const float4*)&sp[0 * HS + jb + q * 4];
                Ev.v[q] = *(const float4*)&sp[1 * HS + jb + q * 4];
                Av.v[q] = *(const float4*)&sp[2 * HS + jb + q * 4];
                Bv.v[q] = *(const float4*)&sp[3 * HS + jb + q * 4];
                Kv.v[q] = *(const float4*)&sp[4 * HS + jb + q * 4];
            }
            const float vt = sp[5 * HS + vrow];

            u64 sacc0 = mul2(S.u[0], Av.u[0]);
            u64 sacc1 = mul2(S.u[1], Av.u[1]);
#pragma unroll
            for (int q = 2; q < 8; q += 2) {
                sacc0 = fma2(S.u[q],     Av.u[q],     sacc0);
                sacc1 = fma2(S.u[q + 1], Av.u[q + 1], sacc1);
            }
            float2 sp2 = unpack2(add2(sacc0, sacc1));
            float sal = sp2.x + sp2.y;
            float sA = __shfl_xor_sync(0xffffffffu, sal, 1);
            float sB = __shfl_xor_sync(0xffffffffu, sal, 2);
            float sC = __shfl_xor_sync(0xffffffffu, sal, 3);

            u64 vt2 = pack2(vt, vt);
            u64 pre[8];
#pragma unroll
            for (int q = 0; q < 8; q++)
                pre[q] = fma2(S.u[q], Ev.u[q], mul2(vt2, Kv.u[q]));

            float sa = (sal + sA) + (sB + sC);
            u64 sa2 = pack2(sa, sa);

            u64 oa0 = 0ull, oa1 = 0ull;
#pragma unroll
            for (int q = 0; q < 8; q += 2) {
                S.u[q]     = fma2(sa2, Bv.u[q],     pre[q]);
                S.u[q + 1] = fma2(sa2, Bv.u[q + 1], pre[q + 1]);
                oa0 = fma2(S.u[q],     Rv.u[q],     oa0);
                oa1 = fma2(S.u[q + 1], Rv.u[q + 1], oa1);
            }
            float2 op2 = unpack2(add2(oa0, oa1));
            o_l = op2.x + op2.y;
            os1 = __shfl_xor_sync(0xffffffffu, o_l, 1);
            os2 = __shfl_xor_sync(0xffffffffu, o_l, 2);
            os3 = __shfl_xor_sync(0xffffffffu, o_l, 3);
        }

        ISSUE_CHUNK(c + 3)
    }
    if (jg == 0)
        y[(size_t)(T - 1) * C + ybase] = (o_l + os1) + (os2 + os3);
#undef ISSUE_CHUNK
}

// ---------------- K7: GroupNorm + bonus + gate ----------------
__global__ void k_gn(const float* __restrict__ y, const float* __restrict__ r,
                     const float* __restrict__ kadj, const float* __restrict__ v,
                     const float* __restrict__ gg, const float* __restrict__ rk,
                     const float* __restrict__ lnw, const float* __restrict__ lnb,
                     float* __restrict__ z) {
    const int t = blockIdx.x;
    const int tid = threadIdx.x;
    const int cbase = tid * 4;
    const size_t idx = (size_t)t * C + cbase;
    float4 yv = *(const float4*)(y + idx);
    float s1 = yv.x + yv.y + yv.z + yv.w;
    float s2 = yv.x * yv.x + yv.y * yv.y + yv.z * yv.z + yv.w * yv.w;
    float4 rv = *(const float4*)(r + idx);
    float4 kv = *(const float4*)(kadj + idx);
    float4 rkv = *(const float4*)(rk + cbase);
    float s3 = rv.x * kv.x * rkv.x + rv.y * kv.y * rkv.y +
               rv.z * kv.z * rkv.z + rv.w * kv.w * rkv.w;
#pragma unroll
    for (int off = 8; off > 0; off >>= 1) {
        s1 += __shfl_xor_sync(0xffffffffu, s1, off);
        s2 += __shfl_xor_sync(0xffffffffu, s2, off);
        s3 += __shfl_xor_sync(0xffffffffu, s3, off);
    }
    const float mu = s1 * (1.f / HS);
    const float var = s2 * (1.f / HS) - mu * mu;
    const float inv = rsqrtf(var + EPS_GN);
    float4 vv = *(const float4*)(v + idx);
    float4 gv = *(const float4*)(gg + idx);
    float4 lw = *(const float4*)(lnw + cbase);
    float4 lb = *(const float4*)(lnb + cbase);
    float4 res;
    res.x = (fmaf((yv.x - mu) * inv, lw.x, lb.x) + s3 * vv.x) * gv.x;
    res.y = (fmaf((yv.y - mu) * inv, lw.y, lb.y) + s3 * vv.y) * gv.y;
    res.z = (fmaf((yv.z - mu) * inv, lw.z, lb.z) + s3 * vv.z) * gv.z;
    res.w = (fmaf((yv.w - mu) * inv, lw.w, lb.w) + s3 * vv.w) * gv.w;
    *(float4*)(z + idx) = res;
}

// ---------------- launch ----------------
extern "C" void kernel_launch(void* const* d_in, const int* in_sizes, int n_in,
                              void* d_out, int out_size) {
    const float* x       = (const float*)d_in[0];
    const float* v_first = (const float*)d_in[1];
    const float* x_prev  = (const float*)d_in[2];
    const float* S0      = (const float*)d_in[3];
    const float* m_r = (const float*)d_in[4];
    const float* m_w = (const float*)d_in[5];
    const float* m_k = (const float*)d_in[6];
    const float* m_v = (const float*)d_in[7];
    const float* m_a = (const float*)d_in[8];
    const float* m_g = (const float*)d_in[9];

    const float *w0, *w1, *w2, *a0, *a1, *a2, *v0, *v1, *v2, *g1, *g2, *k_k, *k_a, *r_k;
    if (in_sizes[11] == C) {
        w0 = (const float*)d_in[10]; a0 = (const float*)d_in[11];
        v0 = (const float*)d_in[12]; k_k = (const float*)d_in[13];
        k_a = (const float*)d_in[14];
        w1 = (const float*)d_in[15]; w2 = (const float*)d_in[16];
        a1 = (const float*)d_in[17]; a2 = (const float*)d_in[18];
        v1 = (const float*)d_in[19]; v2 = (const float*)d_in[20];
        g1 = (const float*)d_in[21]; g2 = (const float*)d_in[22];
        r_k = (const float*)d_in[23];
    } else {
        w0 = (const float*)d_in[10]; w1 = (const float*)d_in[11];
        w2 = (const float*)d_in[12];
        a0 = (const float*)d_in[13]; a1 = (const float*)d_in[14];
        a2 = (const float*)d_in[15];
        v0 = (const float*)d_in[16]; v1 = (const float*)d_in[17];
        v2 = (const float*)d_in[18];
        g1 = (const float*)d_in[19]; g2 = (const float*)d_in[20];
        k_k = (const float*)d_in[21]; k_a = (const float*)d_in[22];
        r_k = (const float*)d_in[23];
    }

    const float* Wr = (const float*)d_in[24];
    const float* Wk = (const float*)d_in[25];
    const float* Wv = (const float*)d_in[26];
    const float* Wo = (const float*)d_in[27];
    const float* lnw = (const float*)d_in[28];
    const float* lnb = (const float*)d_in[29];
    const int*   cu  = (const int*)d_in[30];
    const int ncu = in_sizes[30];
    float* out = (float*)d_out;

    float* s = nullptr;
    cudaGetSymbolAddress((void**)&s, g_scratch);
    const size_t P = (size_t)T * C;
    float* xr = s;          float* xw = s + P;      float* xk = s + 2 * P;
    float* xv = s + 3 * P;  float* xa = s + 4 * P;  float* xg = s + 5 * P;
    float* rb = s + 6 * P;  float* kb = s + 7 * P;  float* vbuf = s + 8 * P;
    float* ewb = s + 9 * P; float* ab = s + 10 * P; float* gbuf = s + 11 * P;
    float* aab = s + 12 * P; float* bbb = s + 13 * P; float* kadj = s + 14 * P;
    float* yb = s + 15 * P;  float* zb = s + 16 * P;
    float* hw = s + 17 * P;
    float* ha = hw + (size_t)T * 64;
    float* hv = ha + (size_t)T * 64;
    float* hg = hv + (size_t)T * 32;

    k_shift_mix<<<T, 256>>>(x, x_prev, cu, ncu, m_r, m_w, m_k, m_v, m_a, m_g,
                            xr, xw, xk, xv, xa, xg);

    dim3 gemm_grid(C / 128, T / 128);    // (8, 16) = 128 CTAs
    k_gemm_mma<<<gemm_grid, 256>>>(xr, Wr, rb);
    k_gemm_mma<<<gemm_grid, 256>>>(xk, Wk, kb);
    k_gemm_mma<<<gemm_grid, 256>>>(xv, Wv, vbuf);

    k_stage1<64, 1><<<T / 32, 256>>>(xw, w1, hw);
    k_stage1<64, 0><<<T / 32, 256>>>(xa, a1, ha);
    k_stage1<32, 0><<<T / 32, 256>>>(xv, v1, hv);
    k_stage1<128, 2><<<T / 32, 256>>>(xg, g1, hg);

    dim3 s2grid(C / 128, T / 16);
    k_stage2<64, 0><<<s2grid, 128>>>(hw, w2, w0, nullptr, nullptr, ewb);
    k_stage2<64, 1><<<s2grid, 128>>>(ha, a2, a0, nullptr, nullptr, ab);
    k_stage2<32, 2><<<s2grid, 128>>>(hv, v2, v0, vbuf, v_first, vbuf);
    k_stage2<128, 3><<<s2grid, 128>>>(hg, g2, nullptr, nullptr, nullptr, gbuf);

    k_prep<<<T, 256>>>(kb, ab, k_k, k_a, aab, bbb, kadj);

    k_scan<<<dim3(NH, 8), 32>>>(rb, ewb, aab, bbb, kadj, vbuf, S0, yb);

    k_gn<<<T, 256>>>(yb, rb, kadj, vbuf, gbuf, r_k, lnw, lnb, zb);

    k_gemm_mma<<<gemm_grid, 256>>>(zb, Wo, out);
}

// round 10
// speedup vs baseline: 1.4204x; 1.0046x over previous
#include <cuda_runtime.h>
#include <math.h>

static const int T  = 2048;
static const int C  = 1024;
static const int NH = 16;
static const int HS = 64;
#define EPS_GN 0.00064f

typedef unsigned long long u64;
typedef unsigned int u32;

// ---------------- f32x2 packed helpers ----------------
__device__ __forceinline__ u64 fma2(u64 a, u64 b, u64 c) {
    u64 d; asm("fma.rn.f32x2 %0, %1, %2, %3;" : "=l"(d) : "l"(a), "l"(b), "l"(c)); return d;
}
__device__ __forceinline__ u64 mul2(u64 a, u64 b) {
    u64 d; asm("mul.rn.f32x2 %0, %1, %2;" : "=l"(d) : "l"(a), "l"(b)); return d;
}
__device__ __forceinline__ u64 add2(u64 a, u64 b) {
    u64 d; asm("add.rn.f32x2 %0, %1, %2;" : "=l"(d) : "l"(a), "l"(b)); return d;
}
__device__ __forceinline__ u64 pack2(float lo, float hi) {
    u64 d; asm("mov.b64 %0, {%1, %2};" : "=l"(d) : "f"(lo), "f"(hi)); return d;
}
__device__ __forceinline__ float2 unpack2(u64 v) {
    float2 r; asm("mov.b64 {%0, %1}, %2;" : "=f"(r.x), "=f"(r.y) : "l"(v)); return r;
}
__device__ __forceinline__ void cp16(unsigned s, const float* g) {
    asm volatile("cp.async.ca.shared.global [%0], [%1], 16;" :: "r"(s), "l"(g));
}

// ---------------- scratch ----------------
__device__ float g_scratch[(size_t)17 * 2048 * 1024 + (size_t)2048 * 288];

// ---------------- K1: token shift + 6-way mix ----------------
__global__ void k_shift_mix(const float* __restrict__ x, const float* __restrict__ x_prev,
                            const int* __restrict__ cu, int ncu,
                            const float* __restrict__ mr, const float* __restrict__ mw,
                            const float* __restrict__ mk, const float* __restrict__ mv,
                            const float* __restrict__ ma, const float* __restrict__ mg,
                            float* __restrict__ oxr, float* __restrict__ oxw,
                            float* __restrict__ oxk, float* __restrict__ oxv,
                            float* __restrict__ oxa, float* __restrict__ oxg) {
    const int t = blockIdx.x;
    int kind = (t == 0) ? 1 : 0;
    int prow = 0;
    for (int i = 0; i + 1 < ncu; i++) if (cu[i] == t) { kind = 2; prow = i; }
    const int c = threadIdx.x * 4;
    const size_t off = (size_t)t * C + c;
    float4 xc = *(const float4*)(x + off);
    float4 pv;
    if (kind == 0)      pv = *(const float4*)(x + off - C);
    else if (kind == 2) pv = *(const float4*)(x_prev + (size_t)prow * C + c);
    else                pv = make_float4(0.f, 0.f, 0.f, 0.f);
    float4 dx = make_float4(pv.x - xc.x, pv.y - xc.y, pv.z - xc.z, pv.w - xc.w);
#define MIXOUT(dst, m) { \
    float4 mm = *(const float4*)((m) + c); \
    float4 r_ = make_float4(fmaf(dx.x, mm.x, xc.x), fmaf(dx.y, mm.y, xc.y), \
                            fmaf(dx.z, mm.z, xc.z), fmaf(dx.w, mm.w, xc.w)); \
    *(float4*)((dst) + off) = r_; }
    MIXOUT(oxr, mr) MIXOUT(oxw, mw) MIXOUT(oxk, mk)
    MIXOUT(oxv, mv) MIXOUT(oxa, ma) MIXOUT(oxg, mg)
#undef MIXOUT
}

// ---------------- K2: bf16x3 mma.sync NT GEMM, double-buffered smem -------------------
#define SROW 18
#define STAGE_U32 (128 * SROW)

#define MMA_BF16(ac, av, bv) \
    asm volatile("mma.sync.aligned.m16n8k16.row.col.f32.bf16.bf16.f32 " \
        "{%0,%1,%2,%3},{%4,%5,%6,%7},{%8,%9},{%0,%1,%2,%3};" \
        : "+f"((ac)[0]), "+f"((ac)[1]), "+f"((ac)[2]), "+f"((ac)[3]) \
        : "r"((av)[0]), "r"((av)[1]), "r"((av)[2]), "r"((av)[3]), \
          "r"((bv)[0]), "r"((bv)[1]))

__global__ void __launch_bounds__(256) k_gemm_mma(const float* __restrict__ A,
                                                  const float* __restrict__ B,
                                                  float* __restrict__ Cg) {
    extern __shared__ u32 smem_dyn[];
    // layout: [stage][Ah|Al|Bh|Bl], each STAGE_U32/... : 4 arrays per stage
    const int bm = blockIdx.y * 128;
    const int bn = blockIdx.x * 128;
    const int tid = threadIdx.x;
    const int wid = tid >> 5;
    const int lane = tid & 31;
    const int wm = (wid & 1) * 64;
    const int wn = (wid >> 1) * 32;
    const int g = lane >> 2;
    const int tg = lane & 3;

    float acc[4][4][4];
#pragma unroll
    for (int mt = 0; mt < 4; mt++)
#pragma unroll
        for (int nt = 0; nt < 4; nt++)
#pragma unroll
            for (int q = 0; q < 4; q++) acc[mt][nt][q] = 0.f;

    float2 aPre[8], bPre[8];
#define LDG_CHUNK(cc) { \
    _Pragma("unroll") \
    for (int i = 0; i < 8; i++) { \
        const int p = i * 256 + tid; \
        const int row = p >> 4; \
        const int kk = (p & 15) * 2; \
        aPre[i] = *(const float2*)(A + (size_t)(bm + row) * C + (cc) * 32 + kk); \
        bPre[i] = *(const float2*)(B + (size_t)(bn + row) * C + (cc) * 32 + kk); \
    } }

#define SPLIT_STORE(f2, Hbuf, Lbuf, w) { \
    u32 bx_ = __float_as_uint((f2).x), by_ = __float_as_uint((f2).y); \
    u32 hx_ = bx_ & 0xFFFF0000u, hy_ = by_ & 0xFFFF0000u; \
    (Hbuf)[w] = (hx_ >> 16) | hy_; \
    float lx_ = (f2).x - __uint_as_float(hx_); \
    float ly_ = (f2).y - __uint_as_float(hy_); \
    u32 lp_; \
    asm("cvt.rn.satfinite.bf16x2.f32 %0, %1, %2;" : "=r"(lp_) : "f"(ly_), "f"(lx_)); \
    (Lbuf)[w] = lp_; }

#define STS_CHUNK(st) { \
    u32* Ah_ = smem_dyn + (st) * 4 * STAGE_U32; \
    u32* Al_ = Ah_ + STAGE_U32; \
    u32* Bh_ = Al_ + STAGE_U32; \
    u32* Bl_ = Bh_ + STAGE_U32; \
    _Pragma("unroll") \
    for (int i = 0; i < 8; i++) { \
        const int p = i * 256 + tid; \
        const int row = p >> 4; \
        const int colw = p & 15; \
        const u32 w_ = (u32)(row * SROW + colw); \
        SPLIT_STORE(aPre[i], Ah_, Al_, w_) \
        SPLIT_STORE(bPre[i], Bh_, Bl_, w_) \
    } }

    LDG_CHUNK(0)
    STS_CHUNK(0)
    __syncthreads();
    LDG_CHUNK(1)

    const int NCHUNK = C / 32;
    for (int c = 0; c < NCHUNK; c++) {
        const u32* Ah = smem_dyn + (c & 1) * 4 * STAGE_U32;
        const u32* Al = Ah + STAGE_U32;
        const u32* Bh = Al + STAGE_U32;
        const u32* Bl = Bh + STAGE_U32;

        // stage next chunk into the other buffer (overlaps with MMAs below)
        if (c + 1 < NCHUNK) {
            STS_CHUNK((c + 1) & 1)
        }
        if (c + 2 < NCHUNK) LDG_CHUNK(c + 2)

#pragma unroll
        for (int k16 = 0; k16 < 2; k16++) {
            const int colb = k16 * 8 + tg;

            u32 aH[4][4];
#pragma unroll
            for (int mt = 0; mt < 4; mt++) {
                const int base = (wm + mt * 16 + g) * SROW + colb;
                aH[mt][0] = Ah[base];
                aH[mt][1] = Ah[base + 8 * SROW];
                aH[mt][2] = Ah[base + 4];
                aH[mt][3] = Ah[base + 8 * SROW + 4];
            }
            u32 bH[4][2];
#pragma unroll
            for (int nt = 0; nt < 4; nt++) {
                const int base = (wn + nt * 8 + g) * SROW + colb;
                bH[nt][0] = Bh[base];
                bH[nt][1] = Bh[base + 4];
            }
#pragma unroll
            for (int mt = 0; mt < 4; mt++)
#pragma unroll
                for (int nt = 0; nt < 4; nt++)
                    MMA_BF16(acc[mt][nt], aH[mt], bH[nt]);

            u32 bL[4][2];
#pragma unroll
            for (int nt = 0; nt < 4; nt++) {
                const int base = (wn + nt * 8 + g) * SROW + colb;
                bL[nt][0] = Bl[base];
                bL[nt][1] = Bl[base + 4];
            }
#pragma unroll
            for (int mt = 0; mt < 4; mt++)
#pragma unroll
                for (int nt = 0; nt < 4; nt++)
                    MMA_BF16(acc[mt][nt], aH[mt], bL[nt]);

            u32 aL[4][4];
#pragma unroll
            for (int mt = 0; mt < 4; mt++) {
                const int base = (wm + mt * 16 + g) * SROW + colb;
                aL[mt][0] = Al[base];
                aL[mt][1] = Al[base + 8 * SROW];
                aL[mt][2] = Al[base + 4];
                aL[mt][3] = Al[base + 8 * SROW + 4];
            }
#pragma unroll
            for (int mt = 0; mt < 4; mt++)
#pragma unroll
                for (int nt = 0; nt < 4; nt++)
                    MMA_BF16(acc[mt][nt], aL[mt], bH[nt]);
        }
        __syncthreads();
    }

#pragma unroll
    for (int mt = 0; mt < 4; mt++) {
#pragma unroll
        for (int nt = 0; nt < 4; nt++) {
            const int row = bm + wm + mt * 16 + g;
            const int col = bn + wn + nt * 8 + tg * 2;
            *(float2*)(Cg + (size_t)row * C + col) =
                make_float2(acc[mt][nt][0], acc[mt][nt][1]);
            *(float2*)(Cg + (size_t)(row + 8) * C + col) =
                make_float2(acc[mt][nt][2], acc[mt][nt][3]);
        }
    }
#undef LDG_CHUNK
#undef STS_CHUNK
#undef SPLIT_STORE
}

// ---------------- K3: stage-1 LoRA GEMM ----------------
template <int KO, int ACT>
__global__ void __launch_bounds__(256) k_stage1(const float* __restrict__ X,
                                                const float* __restrict__ W,
                                                float* __restrict__ out) {
    __shared__ float Xs[32][33];
    __shared__ float Ws[32][KO];
    const int t0 = blockIdx.x * 32;
    const int tid = threadIdx.x;
    const int j = tid % KO;
    const int tg = tid / KO;
    const int RPT = 256 / KO;
    const int NT = 32 / RPT;
    float acc[NT];
#pragma unroll
    for (int tt = 0; tt < NT; tt++) acc[tt] = 0.f;

    for (int cb = 0; cb < C; cb += 32) {
#pragma unroll
        for (int i = tid; i < 32 * 32; i += 256)
            Xs[i >> 5][i & 31] = X[(size_t)(t0 + (i >> 5)) * C + cb + (i & 31)];
#pragma unroll
        for (int i = tid; i < 32 * KO; i += 256)
            Ws[i / KO][i % KO] = W[(size_t)(cb + i / KO) * KO + (i % KO)];
        __syncthreads();
#pragma unroll
        for (int cc = 0; cc < 32; cc++) {
            float wv = Ws[cc][j];
#pragma unroll
            for (int tt = 0; tt < NT; tt++)
                acc[tt] = fmaf(Xs[tg * NT + tt][cc], wv, acc[tt]);
        }
        __syncthreads();
    }
#pragma unroll
    for (int tt = 0; tt < NT; tt++) {
        float val = acc[tt];
        if (ACT == 1) val = tanhf(val);
        else if (ACT == 2) val = 1.f / (1.f + expf(-val));
        out[(size_t)(t0 + tg * NT + tt) * KO + j] = val;
    }
}

// ---------------- K4: stage-2 LoRA GEMM + fused epilogue ----------------
template <int KI, int EPI>
__global__ void __launch_bounds__(128) k_stage2(const float* __restrict__ Hh,
                                                const float* __restrict__ W2,
                                                const float* __restrict__ bias,
                                                const float* __restrict__ e1,
                                                const float* __restrict__ e2,
                                                float* __restrict__ out) {
    __shared__ float Hs[16][KI];
    const int tb = blockIdx.y * 16;
    const int o = blockIdx.x * 128 + threadIdx.x;
    for (int i = threadIdx.x; i < 16 * KI; i += 128)
        Hs[i / KI][i % KI] = Hh[(size_t)(tb + i / KI) * KI + (i % KI)];
    __syncthreads();
    float acc[16];
#pragma unroll
    for (int t = 0; t < 16; t++) acc[t] = 0.f;
#pragma unroll 8
    for (int cdx = 0; cdx < KI; cdx++) {
        float wv = W2[(size_t)cdx * C + o];
#pragma unroll
        for (int t = 0; t < 16; t++)
            acc[t] = fmaf(Hs[t][cdx], wv, acc[t]);
    }
    float bv = (EPI == 3) ? 0.f : bias[o];
#pragma unroll
    for (int t = 0; t < 16; t++) {
        size_t idx = (size_t)(tb + t) * C + o;
        float zv = acc[t] + bv;
        float res;
        if (EPI == 0) {
            float xn = -zv;
            float sp = (xn > 20.f) ? xn : log1pf(expf(xn));
            res = expf(-expf(-sp - 0.5f));
        } else if (EPI == 1) {
            res = 1.f / (1.f + expf(-zv));
        } else if (EPI == 2) {
            float sg = 1.f / (1.f + expf(-zv));
            float vr = e1[idx];
            res = fmaf(e2[idx] - vr, sg, vr);
        } else {
            res = zv;
        }
        out[idx] = res;
    }
}

// ---------------- K5: scan-input prep ----------------
__global__ void k_prep(const float* __restrict__ kin, const float* __restrict__ ain,
                       const float* __restrict__ kkw, const float* __restrict__ kaw,
                       float* __restrict__ aab, float* __restrict__ bbb,
                       float* __restrict__ kadj) {
    const int t = blockIdx.x;
    const int tid = threadIdx.x;
    const int cbase = tid * 4;
    const size_t idx = (size_t)t * C + cbase;
    float4 kv = *(const float4*)(kin + idx);
    float4 av = *(const float4*)(ain + idx);
    float4 kw = *(const float4*)(kkw + cbase);
    float4 aw = *(const float4*)(kaw + cbase);
    float4 kk = make_float4(kv.x * kw.x, kv.y * kw.y, kv.z * kw.z, kv.w * kw.w);
    float ss = kk.x * kk.x + kk.y * kk.y + kk.z * kk.z + kk.w * kk.w;
#pragma unroll
    for (int off = 8; off > 0; off >>= 1)
        ss += __shfl_xor_sync(0xffffffffu, ss, off);
    float inv = 1.f / fmaxf(sqrtf(ss), 1e-12f);
    float4 kn = make_float4(kk.x * inv, kk.y * inv, kk.z * inv, kk.w * inv);
    *(float4*)(aab + idx) = make_float4(-kn.x, -kn.y, -kn.z, -kn.w);
    *(float4*)(bbb + idx) = make_float4(kn.x * av.x, kn.y * av.y, kn.z * av.z, kn.w * av.w);
    *(float4*)(kadj + idx) = make_float4(
        kv.x * fmaf(av.x - 1.f, aw.x, 1.f),
        kv.y * fmaf(av.y - 1.f, aw.y, 1.f),
        kv.z * fmaf(av.z - 1.f, aw.z, 1.f),
        kv.w * fmaf(av.w - 1.f, aw.w, 1.f));
}

// ---------------- K6: RWKV-7 serial scan (8-step cp.async chunks + FFMA2) -------------
union U16 { float f[16]; u64 u[8]; float4 v[4]; };

#define RING_SLOTS 16
#define CHUNK 8

__global__ void __launch_bounds__(32) k_scan(const float* __restrict__ rb,
                                             const float* __restrict__ ewb,
                                             const float* __restrict__ aab,
                                             const float* __restrict__ bbb,
                                             const float* __restrict__ kb,
                                             const float* __restrict__ vb,
                                             const float* __restrict__ S0,
                                             float* __restrict__ y) {
    __shared__ float ring[RING_SLOTS][6 * HS];
    const int h  = blockIdx.x;
    const int vg = blockIdx.y;
    const int tid = threadIdx.x;
    const int jg = tid & 3;
    const int vr = tid >> 2;
    const int vrow = vg * 8 + vr;
    const int jb = jg * 16;

    U16 S;
#pragma unroll
    for (int q = 0; q < 4; q++)
        S.v[q] = *(const float4*)(S0 + (size_t)h * HS * HS + (size_t)vrow * HS + jb + q * 4);

    const int off16 = (tid & 15) << 2;
    const int arr0 = tid >> 4;
    const int arr1 = arr0 + 2;
    const int arr2 = arr0 + 4;
    const float* s0 = (arr0 == 0 ? rb  : ewb) + (size_t)h * HS + off16;
    const float* s1 = (arr1 == 2 ? aab : bbb) + (size_t)h * HS + off16;
    const float* s2 = (arr2 == 4 ? kb  : vb ) + (size_t)h * HS + off16;
    unsigned base_u = (unsigned)__cvta_generic_to_shared(&ring[0][0]);
    const unsigned d0 = base_u + (unsigned)(arr0 * HS + off16) * 4u;
    const unsigned d1 = base_u + (unsigned)(arr1 * HS + off16) * 4u;
    const unsigned d2 = base_u + (unsigned)(arr2 * HS + off16) * 4u;

#define ISSUE_CHUNK(cb) { \
    _Pragma("unroll") \
    for (int s_ = 0; s_ < CHUNK; s_++) { \
        int st_ = (cb) * CHUNK + s_; \
        int slot_ = st_ & (RING_SLOTS - 1); \
        if (st_ >= T) st_ = T - 1; \
        size_t so_ = (size_t)st_ * C; \
        unsigned sb_ = (unsigned)slot_ * (6 * HS * 4); \
        cp16(d0 + sb_, s0 + so_); \
        cp16(d1 + sb_, s1 + so_); \
        cp16(d2 + sb_, s2 + so_); \
    } \
    asm volatile("cp.async.commit_group;"); }

    ISSUE_CHUNK(0)
    ISSUE_CHUNK(1)

    float o_l = 0.f, os1 = 0.f, os2 = 0.f, os3 = 0.f;
    const size_t ybase = (size_t)h * HS + vrow;
    const int NCH = T / CHUNK;

    for (int c = 0; c < NCH; c++) {
        asm volatile("cp.async.wait_group 1;");   // chunk c complete
        __syncwarp();

#pragma unroll
        for (int s = 0; s < CHUNK; s++) {
            const int t = c * CHUNK + s;
            if (t > 0 && jg == 0)
                y[(size_t)(t - 1) * C + ybase] = (o_l + os1) + (os2 + os3);

            const float* sp = &ring[t & (RING_SLOTS - 1)][0];
            U16 Rv, Ev, Av, Bv, Kv;
#pragma unroll
            for (int q = 0; q < 4; q++) {
                Rv.v[q] = *(const float4*)&sp[0 * HS + jb + q * 4];
                Ev.v[q] = *(const float4*)&sp[1 * HS + jb + q * 4];
                Av.v[q] = *(const float4*)&sp[2 * HS + jb + q * 4];
                Bv.v[q] = *(const float4*)&sp[3 * HS + jb + q * 4];
                Kv.v[q] = *(const float4*)&sp[4 * HS + jb + q * 4];
            }
            const float vt = sp[5 * HS + vrow];

            u64 sacc0 = mul2(S.u[0], Av.u[0]);
            u64 sacc1 = mul2(S.u[1], Av.u[1]);
#pragma unroll
            for (int q = 2; q < 8; q += 2) {
                sacc0 = fma2(S.u[q],     Av.u[q],     sacc0);
                sacc1 = fma2(S.u[q + 1], Av.u[q + 1], sacc1);
            }
            float2 sp2 = unpack2(add2(sacc0, sacc1));
            float sal = sp2.x + sp2.y;
            float sA = __shfl_xor_sync(0xffffffffu, sal, 1);
            float sB = __shfl_xor_sync(0xffffffffu, sal, 2);
            float sC = __shfl_xor_sync(0xffffffffu, sal, 3);

            u64 vt2 = pack2(vt, vt);
            u64 pre[8];
#pragma unroll
            for (int q = 0; q < 8; q++)
                pre[q] = fma2(S.u[q], Ev.u[q], mul2(vt2, Kv.u[q]));

            float sa = (sal + sA) + (sB + sC);
            u64 sa2 = pack2(sa, sa);

            u64 oa0 = 0ull, oa1 = 0ull;
#pragma unroll
            for (int q = 0; q < 8; q += 2) {
                S.u[q]     = fma2(sa2, Bv.u[q],     pre[q]);
                S.u[q + 1] = fma2(sa2, Bv.u[q + 1], pre[q + 1]);
                oa0 = fma2(S.u[q],     Rv.u[q],     oa0);
                oa1 = fma2(S.u[q + 1], Rv.u[q + 1], oa1);
            }
            float2 op2 = unpack2(add2(oa0, oa1));
            o_l = op2.x + op2.y;
            os1 = __shfl_xor_sync(0xffffffffu, o_l, 1);
            os2 = __shfl_xor_sync(0xffffffffu, o_l, 2);
            os3 = __shfl_xor_sync(0xffffffffu, o_l, 3);
        }

        ISSUE_CHUNK(c + 2)
    }
    if (jg == 0)
        y[(size_t)(T - 1) * C + ybase] = (o_l + os1) + (os2 + os3);
#undef ISSUE_CHUNK
}

// ---------------- K7: GroupNorm + bonus + gate ----------------
__global__ void k_gn(const float* __restrict__ y, const float* __restrict__ r,
                     const float* __restrict__ kadj, const float* __restrict__ v,
                     const float* __restrict__ gg, const float* __restrict__ rk,
                     const float* __restrict__ lnw, const float* __restrict__ lnb,
                     float* __restrict__ z) {
    const int t = blockIdx.x;
    const int tid = threadIdx.x;
    const int cbase = tid * 4;
    const size_t idx = (size_t)t * C + cbase;
    float4 yv = *(const float4*)(y + idx);
    float s1 = yv.x + yv.y + yv.z + yv.w;
    float s2 = yv.x * yv.x + yv.y * yv.y + yv.z * yv.z + yv.w * yv.w;
    float4 rv = *(const float4*)(r + idx);
    float4 kv = *(const float4*)(kadj + idx);
    float4 rkv = *(const float4*)(rk + cbase);
    float s3 = rv.x * kv.x * rkv.x + rv.y * kv.y * rkv.y +
               rv.z * kv.z * rkv.z + rv.w * kv.w * rkv.w;
#pragma unroll
    for (int off = 8; off > 0; off >>= 1) {
        s1 += __shfl_xor_sync(0xffffffffu, s1, off);
        s2 += __shfl_xor_sync(0xffffffffu, s2, off);
        s3 += __shfl_xor_sync(0xffffffffu, s3, off);
    }
    const float mu = s1 * (1.f / HS);
    const float var = s2 * (1.f / HS) - mu * mu;
    const float inv = rsqrtf(var + EPS_GN);
    float4 vv = *(const float4*)(v + idx);
    float4 gv = *(const float4*)(gg + idx);
    float4 lw = *(const float4*)(lnw + cbase);
    float4 lb = *(const float4*)(lnb + cbase);
    float4 res;
    res.x = (fmaf((yv.x - mu) * inv, lw.x, lb.x) + s3 * vv.x) * gv.x;
    res.y = (fmaf((yv.y - mu) * inv, lw.y, lb.y) + s3 * vv.y) * gv.y;
    res.z = (fmaf((yv.z - mu) * inv, lw.z, lb.z) + s3 * vv.z) * gv.z;
    res.w = (fmaf((yv.w - mu) * inv, lw.w, lb.w) + s3 * vv.w) * gv.w;
    *(float4*)(z + idx) = res;
}

// ---------------- launch ----------------
extern "C" void kernel_launch(void* const* d_in, const int* in_sizes, int n_in,
                              void* d_out, int out_size) {
    const float* x       = (const float*)d_in[0];
    const float* v_first = (const float*)d_in[1];
    const float* x_prev  = (const float*)d_in[2];
    const float* S0      = (const float*)d_in[3];
    const float* m_r = (const float*)d_in[4];
    const float* m_w = (const float*)d_in[5];
    const float* m_k = (const float*)d_in[6];
    const float* m_v = (const float*)d_in[7];
    const float* m_a = (const float*)d_in[8];
    const float* m_g = (const float*)d_in[9];

    const float *w0, *w1, *w2, *a0, *a1, *a2, *v0, *v1, *v2, *g1, *g2, *k_k, *k_a, *r_k;
    if (in_sizes[11] == C) {
        w0 = (const float*)d_in[10]; a0 = (const float*)d_in[11];
        v0 = (const float*)d_in[12]; k_k = (const float*)d_in[13];
        k_a = (const float*)d_in[14];
        w1 = (const float*)d_in[15]; w2 = (const float*)d_in[16];
        a1 = (const float*)d_in[17]; a2 = (const float*)d_in[18];
        v1 = (const float*)d_in[19]; v2 = (const float*)d_in[20];
        g1 = (const float*)d_in[21]; g2 = (const float*)d_in[22];
        r_k = (const float*)d_in[23];
    } else {
        w0 = (const float*)d_in[10]; w1 = (const float*)d_in[11];
        w2 = (const float*)d_in[12];
        a0 = (const float*)d_in[13]; a1 = (const float*)d_in[14];
        a2 = (const float*)d_in[15];
        v0 = (const float*)d_in[16]; v1 = (const float*)d_in[17];
        v2 = (const float*)d_in[18];
        g1 = (const float*)d_in[19]; g2 = (const float*)d_in[20];
        k_k = (const float*)d_in[21]; k_a = (const float*)d_in[22];
        r_k = (const float*)d_in[23];
    }

    const float* Wr = (const float*)d_in[24];
    const float* Wk = (const float*)d_in[25];
    const float* Wv = (const float*)d_in[26];
    const float* Wo = (const float*)d_in[27];
    const float* lnw = (const float*)d_in[28];
    const float* lnb = (const float*)d_in[29];
    const int*   cu  = (const int*)d_in[30];
    const int ncu = in_sizes[30];
    float* out = (float*)d_out;

    float* s = nullptr;
    cudaGetSymbolAddress((void**)&s, g_scratch);
    const size_t P = (size_t)T * C;
    float* xr = s;          float* xw = s + P;      float* xk = s + 2 * P;
    float* xv = s + 3 * P;  float* xa = s + 4 * P;  float* xg = s + 5 * P;
    float* rb = s + 6 * P;  float* kb = s + 7 * P;  float* vbuf = s + 8 * P;
    float* ewb = s + 9 * P; float* ab = s + 10 * P; float* gbuf = s + 11 * P;
    float* aab = s + 12 * P; float* bbb = s + 13 * P; float* kadj = s + 14 * P;
    float* yb = s + 15 * P;  float* zb = s + 16 * P;
    float* hw = s + 17 * P;
    float* ha = hw + (size_t)T * 64;
    float* hv = ha + (size_t)T * 64;
    float* hg = hv + (size_t)T * 32;

    const int GEMM_SMEM = 2 * 4 * STAGE_U32 * 4;   // 2 stages x 4 arrays x 9216B = 73728
    static int smem_set = 0;
    if (!smem_set) {
        cudaFuncSetAttribute(k_gemm_mma, cudaFuncAttributeMaxDynamicSharedMemorySize,
                             GEMM_SMEM);
        smem_set = 1;
    }

    k_shift_mix<<<T, 256>>>(x, x_prev, cu, ncu, m_r, m_w, m_k, m_v, m_a, m_g,
                            xr, xw, xk, xv, xa, xg);

    dim3 gemm_grid(C / 128, T / 128);
    k_gemm_mma<<<gemm_grid, 256, GEMM_SMEM>>>(xr, Wr, rb);
    k_gemm_mma<<<gemm_grid, 256, GEMM_SMEM>>>(xk, Wk, kb);
    k_gemm_mma<<<gemm_grid, 256, GEMM_SMEM>>>(xv, Wv, vbuf);

    k_stage1<64, 1><<<T / 32, 256>>>(xw, w1, hw);
    k_stage1<64, 0><<<T / 32, 256>>>(xa, a1, ha);
    k_stage1<32, 0><<<T / 32, 256>>>(xv, v1, hv);
    k_stage1<128, 2><<<T / 32, 256>>>(xg, g1, hg);

    dim3 s2grid(C / 128, T / 16);
    k_stage2<64, 0><<<s2grid, 128>>>(hw, w2, w0, nullptr, nullptr, ewb);
    k_stage2<64, 1><<<s2grid, 128>>>(ha, a2, a0, nullptr, nullptr, ab);
    k_stage2<32, 2><<<s2grid, 128>>>(hv, v2, v0, vbuf, v_first, vbuf);
    k_stage2<128, 3><<<s2grid, 128>>>(hg, g2, nullptr, nullptr, nullptr, gbuf);

    k_prep<<<T, 256>>>(kb, ab, k_k, k_a, aab, bbb, kadj);

    k_scan<<<dim3(NH, 8), 32>>>(rb, ewb, aab, bbb, kadj, vbuf, S0, yb);

    k_gn<<<T, 256>>>(yb, rb, kadj, vbuf, gbuf, r_k, lnw, lnb, zb);

    k_gemm_mma<<<gemm_grid, 256, GEMM_SMEM>>>(zb, Wo, out);
}

// round 11
// speedup vs baseline: 1.5819x; 1.1137x over previous
#include <cuda_runtime.h>
#include <math.h>

static const int T  = 2048;
static const int C  = 1024;
static const int NH = 16;
static const int HS = 64;
#define EPS_GN 0.00064f

typedef unsigned long long u64;
typedef unsigned int u32;

// ---------------- f32x2 packed helpers ----------------
__device__ __forceinline__ u64 fma2(u64 a, u64 b, u64 c) {
    u64 d; asm("fma.rn.f32x2 %0, %1, %2, %3;" : "=l"(d) : "l"(a), "l"(b), "l"(c)); return d;
}
__device__ __forceinline__ u64 mul2(u64 a, u64 b) {
    u64 d; asm("mul.rn.f32x2 %0, %1, %2;" : "=l"(d) : "l"(a), "l"(b)); return d;
}
__device__ __forceinline__ u64 add2(u64 a, u64 b) {
    u64 d; asm("add.rn.f32x2 %0, %1, %2;" : "=l"(d) : "l"(a), "l"(b)); return d;
}
__device__ __forceinline__ u64 pack2(float lo, float hi) {
    u64 d; asm("mov.b64 %0, {%1, %2};" : "=l"(d) : "f"(lo), "f"(hi)); return d;
}
__device__ __forceinline__ float2 unpack2(u64 v) {
    float2 r; asm("mov.b64 {%0, %1}, %2;" : "=f"(r.x), "=f"(r.y) : "l"(v)); return r;
}
__device__ __forceinline__ void cp16(unsigned s, const float* g) {
    asm volatile("cp.async.ca.shared.global [%0], [%1], 16;" :: "r"(s), "l"(g));
}

// ---------------- scratch ----------------
__device__ float g_scratch[(size_t)17 * 2048 * 1024 + (size_t)2048 * 288];

// ---------------- K1: token shift + 6-way mix ----------------
__global__ void k_shift_mix(const float* __restrict__ x, const float* __restrict__ x_prev,
                            const int* __restrict__ cu, int ncu,
                            const float* __restrict__ mr, const float* __restrict__ mw,
                            const float* __restrict__ mk, const float* __restrict__ mv,
                            const float* __restrict__ ma, const float* __restrict__ mg,
                            float* __restrict__ oxr, float* __restrict__ oxw,
                            float* __restrict__ oxk, float* __restrict__ oxv,
                            float* __restrict__ oxa, float* __restrict__ oxg) {
    const int t = blockIdx.x;
    int kind = (t == 0) ? 1 : 0;
    int prow = 0;
    for (int i = 0; i + 1 < ncu; i++) if (cu[i] == t) { kind = 2; prow = i; }
    const int c = threadIdx.x * 4;
    const size_t off = (size_t)t * C + c;
    float4 xc = *(const float4*)(x + off);
    float4 pv;
    if (kind == 0)      pv = *(const float4*)(x + off - C);
    else if (kind == 2) pv = *(const float4*)(x_prev + (size_t)prow * C + c);
    else                pv = make_float4(0.f, 0.f, 0.f, 0.f);
    float4 dx = make_float4(pv.x - xc.x, pv.y - xc.y, pv.z - xc.z, pv.w - xc.w);
#define MIXOUT(dst, m) { \
    float4 mm = *(const float4*)((m) + c); \
    float4 r_ = make_float4(fmaf(dx.x, mm.x, xc.x), fmaf(dx.y, mm.y, xc.y), \
                            fmaf(dx.z, mm.z, xc.z), fmaf(dx.w, mm.w, xc.w)); \
    *(float4*)((dst) + off) = r_; }
    MIXOUT(oxr, mr) MIXOUT(oxw, mw) MIXOUT(oxk, mk)
    MIXOUT(oxv, mv) MIXOUT(oxa, ma) MIXOUT(oxg, mg)
#undef MIXOUT
}

// ---------------- K2: bf16x3 mma.sync NT GEMM, double-buffered, SROW=20 ---------------
#define SROW 20
#define STAGE_U32 (128 * SROW)

#define MMA_BF16(ac, av, bv) \
    asm volatile("mma.sync.aligned.m16n8k16.row.col.f32.bf16.bf16.f32 " \
        "{%0,%1,%2,%3},{%4,%5,%6,%7},{%8,%9},{%0,%1,%2,%3};" \
        : "+f"((ac)[0]), "+f"((ac)[1]), "+f"((ac)[2]), "+f"((ac)[3]) \
        : "r"((av)[0]), "r"((av)[1]), "r"((av)[2]), "r"((av)[3]), \
          "r"((bv)[0]), "r"((bv)[1]))

__global__ void __launch_bounds__(256) k_gemm_mma(const float* __restrict__ A,
                                                  const float* __restrict__ B,
                                                  float* __restrict__ Cg) {
    extern __shared__ u32 smem_dyn[];
    const int bm = blockIdx.y * 128;
    const int bn = blockIdx.x * 128;
    const int tid = threadIdx.x;
    const int wid = tid >> 5;
    const int lane = tid & 31;
    const int wm = (wid & 1) * 64;
    const int wn = (wid >> 1) * 32;
    const int g = lane >> 2;
    const int tg = lane & 3;

    float acc[4][4][4];
#pragma unroll
    for (int mt = 0; mt < 4; mt++)
#pragma unroll
        for (int nt = 0; nt < 4; nt++)
#pragma unroll
            for (int q = 0; q < 4; q++) acc[mt][nt][q] = 0.f;

    float2 aPre[8], bPre[8];
#define LDG_CHUNK(cc) { \
    _Pragma("unroll") \
    for (int i = 0; i < 8; i++) { \
        const int p = i * 256 + tid; \
        const int row = p >> 4; \
        const int kk = (p & 15) * 2; \
        aPre[i] = *(const float2*)(A + (size_t)(bm + row) * C + (cc) * 32 + kk); \
        bPre[i] = *(const float2*)(B + (size_t)(bn + row) * C + (cc) * 32 + kk); \
    } }

#define SPLIT_STORE(f2, Hbuf, Lbuf, w) { \
    u32 bx_ = __float_as_uint((f2).x), by_ = __float_as_uint((f2).y); \
    u32 hx_ = bx_ & 0xFFFF0000u, hy_ = by_ & 0xFFFF0000u; \
    (Hbuf)[w] = (hx_ >> 16) | hy_; \
    float lx_ = (f2).x - __uint_as_float(hx_); \
    float ly_ = (f2).y - __uint_as_float(hy_); \
    u32 lp_; \
    asm("cvt.rn.satfinite.bf16x2.f32 %0, %1, %2;" : "=r"(lp_) : "f"(ly_), "f"(lx_)); \
    (Lbuf)[w] = lp_; }

#define STS_CHUNK(st) { \
    u32* Ah_ = smem_dyn + (st) * 4 * STAGE_U32; \
    u32* Al_ = Ah_ + STAGE_U32; \
    u32* Bh_ = Al_ + STAGE_U32; \
    u32* Bl_ = Bh_ + STAGE_U32; \
    _Pragma("unroll") \
    for (int i = 0; i < 8; i++) { \
        const int p = i * 256 + tid; \
        const int row = p >> 4; \
        const int colw = p & 15; \
        const u32 w_ = (u32)(row * SROW + colw); \
        SPLIT_STORE(aPre[i], Ah_, Al_, w_) \
        SPLIT_STORE(bPre[i], Bh_, Bl_, w_) \
    } }

    LDG_CHUNK(0)
    STS_CHUNK(0)
    __syncthreads();
    LDG_CHUNK(1)

    const int NCHUNK = C / 32;
    for (int c = 0; c < NCHUNK; c++) {
        const u32* Ah = smem_dyn + (c & 1) * 4 * STAGE_U32;
        const u32* Al = Ah + STAGE_U32;
        const u32* Bh = Al + STAGE_U32;
        const u32* Bl = Bh + STAGE_U32;

        if (c + 1 < NCHUNK) {
            STS_CHUNK((c + 1) & 1)
        }
        if (c + 2 < NCHUNK) LDG_CHUNK(c + 2)

#pragma unroll
        for (int k16 = 0; k16 < 2; k16++) {
            const int colb = k16 * 8 + tg;

            u32 aH[4][4];
#pragma unroll
            for (int mt = 0; mt < 4; mt++) {
                const int base = (wm + mt * 16 + g) * SROW + colb;
                aH[mt][0] = Ah[base];
                aH[mt][1] = Ah[base + 8 * SROW];
                aH[mt][2] = Ah[base + 4];
                aH[mt][3] = Ah[base + 8 * SROW + 4];
            }
            u32 bH[4][2];
#pragma unroll
            for (int nt = 0; nt < 4; nt++) {
                const int base = (wn + nt * 8 + g) * SROW + colb;
                bH[nt][0] = Bh[base];
                bH[nt][1] = Bh[base + 4];
            }
#pragma unroll
            for (int mt = 0; mt < 4; mt++)
#pragma unroll
                for (int nt = 0; nt < 4; nt++)
                    MMA_BF16(acc[mt][nt], aH[mt], bH[nt]);

            u32 bL[4][2];
#pragma unroll
            for (int nt = 0; nt < 4; nt++) {
                const int base = (wn + nt * 8 + g) * SROW + colb;
                bL[nt][0] = Bl[base];
                bL[nt][1] = Bl[base + 4];
            }
#pragma unroll
            for (int mt = 0; mt < 4; mt++)
#pragma unroll
                for (int nt = 0; nt < 4; nt++)
                    MMA_BF16(acc[mt][nt], aH[mt], bL[nt]);

            u32 aL[4][4];
#pragma unroll
            for (int mt = 0; mt < 4; mt++) {
                const int base = (wm + mt * 16 + g) * SROW + colb;
                aL[mt][0] = Al[base];
                aL[mt][1] = Al[base + 8 * SROW];
                aL[mt][2] = Al[base + 4];
                aL[mt][3] = Al[base + 8 * SROW + 4];
            }
#pragma unroll
            for (int mt = 0; mt < 4; mt++)
#pragma unroll
                for (int nt = 0; nt < 4; nt++)
                    MMA_BF16(acc[mt][nt], aL[mt], bH[nt]);
        }
        __syncthreads();
    }

#pragma unroll
    for (int mt = 0; mt < 4; mt++) {
#pragma unroll
        for (int nt = 0; nt < 4; nt++) {
            const int row = bm + wm + mt * 16 + g;
            const int col = bn + wn + nt * 8 + tg * 2;
            *(float2*)(Cg + (size_t)row * C + col) =
                make_float2(acc[mt][nt][0], acc[mt][nt][1]);
            *(float2*)(Cg + (size_t)(row + 8) * C + col) =
                make_float2(acc[mt][nt][2], acc[mt][nt][3]);
        }
    }
#undef LDG_CHUNK
#undef STS_CHUNK
#undef SPLIT_STORE
}

// ---------------- K3: stage-1 LoRA GEMM ----------------
template <int KO, int ACT>
__global__ void __launch_bounds__(256) k_stage1(const float* __restrict__ X,
                                                const float* __restrict__ W,
                                                float* __restrict__ out) {
    __shared__ float Xs[32][33];
    __shared__ float Ws[32][KO];
    const int t0 = blockIdx.x * 32;
    const int tid = threadIdx.x;
    const int j = tid % KO;
    const int tg = tid / KO;
    const int RPT = 256 / KO;
    const int NT = 32 / RPT;
    float acc[NT];
#pragma unroll
    for (int tt = 0; tt < NT; tt++) acc[tt] = 0.f;

    for (int cb = 0; cb < C; cb += 32) {
#pragma unroll
        for (int i = tid; i < 32 * 32; i += 256)
            Xs[i >> 5][i & 31] = X[(size_t)(t0 + (i >> 5)) * C + cb + (i & 31)];
#pragma unroll
        for (int i = tid; i < 32 * KO; i += 256)
            Ws[i / KO][i % KO] = W[(size_t)(cb + i / KO) * KO + (i % KO)];
        __syncthreads();
#pragma unroll
        for (int cc = 0; cc < 32; cc++) {
            float wv = Ws[cc][j];
#pragma unroll
            for (int tt = 0; tt < NT; tt++)
                acc[tt] = fmaf(Xs[tg * NT + tt][cc], wv, acc[tt]);
        }
        __syncthreads();
    }
#pragma unroll
    for (int tt = 0; tt < NT; tt++) {
        float val = acc[tt];
        if (ACT == 1) val = tanhf(val);
        else if (ACT == 2) val = 1.f / (1.f + expf(-val));
        out[(size_t)(t0 + tg * NT + tt) * KO + j] = val;
    }
}

// ---------------- K4: stage-2 LoRA GEMM + fused epilogue ----------------
template <int KI, int EPI>
__global__ void __launch_bounds__(128) k_stage2(const float* __restrict__ Hh,
                                                const float* __restrict__ W2,
                                                const float* __restrict__ bias,
                                                const float* __restrict__ e1,
                                                const float* __restrict__ e2,
                                                float* __restrict__ out) {
    __shared__ float Hs[16][KI];
    const int tb = blockIdx.y * 16;
    const int o = blockIdx.x * 128 + threadIdx.x;
    for (int i = threadIdx.x; i < 16 * KI; i += 128)
        Hs[i / KI][i % KI] = Hh[(size_t)(tb + i / KI) * KI + (i % KI)];
    __syncthreads();
    float acc[16];
#pragma unroll
    for (int t = 0; t < 16; t++) acc[t] = 0.f;
#pragma unroll 8
    for (int cdx = 0; cdx < KI; cdx++) {
        float wv = W2[(size_t)cdx * C + o];
#pragma unroll
        for (int t = 0; t < 16; t++)
            acc[t] = fmaf(Hs[t][cdx], wv, acc[t]);
    }
    float bv = (EPI == 3) ? 0.f : bias[o];
#pragma unroll
    for (int t = 0; t < 16; t++) {
        size_t idx = (size_t)(tb + t) * C + o;
        float zv = acc[t] + bv;
        float res;
        if (EPI == 0) {
            float xn = -zv;
            float sp = (xn > 20.f) ? xn : log1pf(expf(xn));
            res = expf(-expf(-sp - 0.5f));
        } else if (EPI == 1) {
            res = 1.f / (1.f + expf(-zv));
        } else if (EPI == 2) {
            float sg = 1.f / (1.f + expf(-zv));
            float vr = e1[idx];
            res = fmaf(e2[idx] - vr, sg, vr);
        } else {
            res = zv;
        }
        out[idx] = res;
    }
}

// ---------------- K5: scan-input prep ----------------
__global__ void k_prep(const float* __restrict__ kin, const float* __restrict__ ain,
                       const float* __restrict__ kkw, const float* __restrict__ kaw,
                       float* __restrict__ aab, float* __restrict__ bbb,
                       float* __restrict__ kadj) {
    const int t = blockIdx.x;
    const int tid = threadIdx.x;
    const int cbase = tid * 4;
    const size_t idx = (size_t)t * C + cbase;
    float4 kv = *(const float4*)(kin + idx);
    float4 av = *(const float4*)(ain + idx);
    float4 kw = *(const float4*)(kkw + cbase);
    float4 aw = *(const float4*)(kaw + cbase);
    float4 kk = make_float4(kv.x * kw.x, kv.y * kw.y, kv.z * kw.z, kv.w * kw.w);
    float ss = kk.x * kk.x + kk.y * kk.y + kk.z * kk.z + kk.w * kk.w;
#pragma unroll
    for (int off = 8; off > 0; off >>= 1)
        ss += __shfl_xor_sync(0xffffffffu, ss, off);
    float inv = 1.f / fmaxf(sqrtf(ss), 1e-12f);
    float4 kn = make_float4(kk.x * inv, kk.y * inv, kk.z * inv, kk.w * inv);
    *(float4*)(aab + idx) = make_float4(-kn.x, -kn.y, -kn.z, -kn.w);
    *(float4*)(bbb + idx) = make_float4(kn.x * av.x, kn.y * av.y, kn.z * av.z, kn.w * av.w);
    *(float4*)(kadj + idx) = make_float4(
        kv.x * fmaf(av.x - 1.f, aw.x, 1.f),
        kv.y * fmaf(av.y - 1.f, aw.y, 1.f),
        kv.z * fmaf(av.z - 1.f, aw.z, 1.f),
        kv.w * fmaf(av.w - 1.f, aw.w, 1.f));
}

// ---------------- K6: RWKV-7 scan — 4 v-rows/block, 256 blocks, cp.async chunks -------
union U8 { float f[8]; u64 u[4]; float4 v[2]; };

#define RING_SLOTS 16
#define CHUNK 8

__global__ void __launch_bounds__(32) k_scan(const float* __restrict__ rb,
                                             const float* __restrict__ ewb,
                                             const float* __restrict__ aab,
                                             const float* __restrict__ bbb,
                                             const float* __restrict__ kb,
                                             const float* __restrict__ vb,
                                             const float* __restrict__ S0,
                                             float* __restrict__ y) {
    __shared__ float ring[RING_SLOTS][6 * HS];
    const int h  = blockIdx.x;
    const int vg = blockIdx.y;           // 0..15
    const int tid = threadIdx.x;
    const int jg = tid & 7;              // 8 j-groups
    const int vr = tid >> 3;             // 4 v-rows
    const int vrow = vg * 4 + vr;
    const int jb = jg * 8;               // 8 j values per thread

    U8 S;
    S.v[0] = *(const float4*)(S0 + (size_t)h * HS * HS + (size_t)vrow * HS + jb);
    S.v[1] = *(const float4*)(S0 + (size_t)h * HS * HS + (size_t)vrow * HS + jb + 4);

    const int off16 = (tid & 15) << 2;
    const int arr0 = tid >> 4;
    const int arr1 = arr0 + 2;
    const int arr2 = arr0 + 4;
    const float* s0 = (arr0 == 0 ? rb  : ewb) + (size_t)h * HS + off16;
    const float* s1 = (arr1 == 2 ? aab : bbb) + (size_t)h * HS + off16;
    const float* s2 = (arr2 == 4 ? kb  : vb ) + (size_t)h * HS + off16;
    unsigned base_u = (unsigned)__cvta_generic_to_shared(&ring[0][0]);
    const unsigned d0 = base_u + (unsigned)(arr0 * HS + off16) * 4u;
    const unsigned d1 = base_u + (unsigned)(arr1 * HS + off16) * 4u;
    const unsigned d2 = base_u + (unsigned)(arr2 * HS + off16) * 4u;

#define ISSUE_CHUNK(cb) { \
    _Pragma("unroll") \
    for (int s_ = 0; s_ < CHUNK; s_++) { \
        int st_ = (cb) * CHUNK + s_; \
        int slot_ = st_ & (RING_SLOTS - 1); \
        if (st_ >= T) st_ = T - 1; \
        size_t so_ = (size_t)st_ * C; \
        unsigned sb_ = (unsigned)slot_ * (6 * HS * 4); \
        cp16(d0 + sb_, s0 + so_); \
        cp16(d1 + sb_, s1 + so_); \
        cp16(d2 + sb_, s2 + so_); \
    } \
    asm volatile("cp.async.commit_group;"); }

    ISSUE_CHUNK(0)
    ISSUE_CHUNK(1)

    float o_l = 0.f, os1 = 0.f, os2 = 0.f, os3 = 0.f;
    const size_t ybase = (size_t)h * HS + vrow;
    const int NCH = T / CHUNK;

    for (int c = 0; c < NCH; c++) {
        asm volatile("cp.async.wait_group 1;");
        __syncwarp();

#pragma unroll
        for (int s = 0; s < CHUNK; s++) {
            const int t = c * CHUNK + s;
            if (t > 0 && jg == 0)
                y[(size_t)(t - 1) * C + ybase] = (o_l + os1) + (os2 + os3);

            const float* sp = &ring[t & (RING_SLOTS - 1)][0];
            U8 Rv, Ev, Av, Bv, Kv;
            Rv.v[0] = *(const float4*)&sp[0 * HS + jb];
            Rv.v[1] = *(const float4*)&sp[0 * HS + jb + 4];
            Ev.v[0] = *(const float4*)&sp[1 * HS + jb];
            Ev.v[1] = *(const float4*)&sp[1 * HS + jb + 4];
            Av.v[0] = *(const float4*)&sp[2 * HS + jb];
            Av.v[1] = *(const float4*)&sp[2 * HS + jb + 4];
            Bv.v[0] = *(const float4*)&sp[3 * HS + jb];
            Bv.v[1] = *(const float4*)&sp[3 * HS + jb + 4];
            Kv.v[0] = *(const float4*)&sp[4 * HS + jb];
            Kv.v[1] = *(const float4*)&sp[4 * HS + jb + 4];
            const float vt = sp[5 * HS + vrow];

            // sa partial over 8 j: two parallel FFMA2 chains
            u64 sacc0 = mul2(S.u[0], Av.u[0]);
            u64 sacc1 = mul2(S.u[1], Av.u[1]);
            sacc0 = fma2(S.u[2], Av.u[2], sacc0);
            sacc1 = fma2(S.u[3], Av.u[3], sacc1);
            float2 sp2 = unpack2(add2(sacc0, sacc1));
            float sal = sp2.x + sp2.y;
            float sA = __shfl_xor_sync(0xffffffffu, sal, 1);
            float sB = __shfl_xor_sync(0xffffffffu, sal, 2);
            float sC = __shfl_xor_sync(0xffffffffu, sal, 4);

            // overlap shfl latency: pre = S*ew + vt*k
            u64 vt2 = pack2(vt, vt);
            u64 pre[4];
#pragma unroll
            for (int q = 0; q < 4; q++)
                pre[q] = fma2(S.u[q], Ev.u[q], mul2(vt2, Kv.u[q]));

            // 8-lane butterfly completion: ((x + x^1) + (x^2 + x^3)) + ...
            float sD = __shfl_xor_sync(0xffffffffu, sA, 2);  // = x^3
            float sE = __shfl_xor_sync(0xffffffffu, sA, 4);  // = x^5
            float sF = __shfl_xor_sync(0xffffffffu, sB, 4);  // = x^6
            float sG = __shfl_xor_sync(0xffffffffu, sD, 4);  // = x^7
            float sa = ((sal + sA) + (sB + sD)) + ((sC + sE) + (sF + sG));
            u64 sa2 = pack2(sa, sa);

            u64 oa0 = 0ull, oa1 = 0ull;
#pragma unroll
            for (int q = 0; q < 4; q += 2) {
                S.u[q]     = fma2(sa2, Bv.u[q],     pre[q]);
                S.u[q + 1] = fma2(sa2, Bv.u[q + 1], pre[q + 1]);
                oa0 = fma2(S.u[q],     Rv.u[q],     oa0);
                oa1 = fma2(S.u[q + 1], Rv.u[q + 1], oa1);
            }
            float2 op2 = unpack2(add2(oa0, oa1));
            o_l = op2.x + op2.y;
            // o reduction across 8 jg lanes: 3 butterfly stages via deferred combine
            float o1 = __shfl_xor_sync(0xffffffffu, o_l, 1);
            float o2p = o_l + o1;
            float o2 = __shfl_xor_sync(0xffffffffu, o2p, 2);
            float o4p = o2p + o2;
            float o4 = __shfl_xor_sync(0xffffffffu, o4p, 4);
            os1 = o4; os2 = o4p; os3 = 0.f;
            o_l = 0.f;
            // store value = o4p + o4; keep in (o_l..os3) form: o_l+os1+os2+os3
            o_l = 0.f; os3 = 0.f; os2 = o4p; os1 = o4;
        }

        ISSUE_CHUNK(c + 2)
    }
    if (jg == 0)
        y[(size_t)(T - 1) * C + ybase] = (o_l + os1) + (os2 + os3);
#undef ISSUE_CHUNK
}

// ---------------- K7: GroupNorm + bonus + gate ----------------
__global__ void k_gn(const float* __restrict__ y, const float* __restrict__ r,
                     const float* __restrict__ kadj, const float* __restrict__ v,
                     const float* __restrict__ gg, const float* __restrict__ rk,
                     const float* __restrict__ lnw, const float* __restrict__ lnb,
                     float* __restrict__ z) {
    const int t = blockIdx.x;
    const int tid = threadIdx.x;
    const int cbase = tid * 4;
    const size_t idx = (size_t)t * C + cbase;
    float4 yv = *(const float4*)(y + idx);
    float s1 = yv.x + yv.y + yv.z + yv.w;
    float s2 = yv.x * yv.x + yv.y * yv.y + yv.z * yv.z + yv.w * yv.w;
    float4 rv = *(const float4*)(r + idx);
    float4 kv = *(const float4*)(kadj + idx);
    float4 rkv = *(const float4*)(rk + cbase);
    float s3 = rv.x * kv.x * rkv.x + rv.y * kv.y * rkv.y +
               rv.z * kv.z * rkv.z + rv.w * kv.w * rkv.w;
#pragma unroll
    for (int off = 8; off > 0; off >>= 1) {
        s1 += __shfl_xor_sync(0xffffffffu, s1, off);
        s2 += __shfl_xor_sync(0xffffffffu, s2, off);
        s3 += __shfl_xor_sync(0xffffffffu, s3, off);
    }
    const float mu = s1 * (1.f / HS);
    const float var = s2 * (1.f / HS) - mu * mu;
    const float inv = rsqrtf(var + EPS_GN);
    float4 vv = *(const float4*)(v + idx);
    float4 gv = *(const float4*)(gg + idx);
    float4 lw = *(const float4*)(lnw + cbase);
    float4 lb = *(const float4*)(lnb + cbase);
    float4 res;
    res.x = (fmaf((yv.x - mu) * inv, lw.x, lb.x) + s3 * vv.x) * gv.x;
    res.y = (fmaf((yv.y - mu) * inv, lw.y, lb.y) + s3 * vv.y) * gv.y;
    res.z = (fmaf((yv.z - mu) * inv, lw.z, lb.z) + s3 * vv.z) * gv.z;
    res.w = (fmaf((yv.w - mu) * inv, lw.w, lb.w) + s3 * vv.w) * gv.w;
    *(float4*)(z + idx) = res;
}

// ---------------- launch ----------------
extern "C" void kernel_launch(void* const* d_in, const int* in_sizes, int n_in,
                              void* d_out, int out_size) {
    const float* x       = (const float*)d_in[0];
    const float* v_first = (const float*)d_in[1];
    const float* x_prev  = (const float*)d_in[2];
    const float* S0      = (const float*)d_in[3];
    const float* m_r = (const float*)d_in[4];
    const float* m_w = (const float*)d_in[5];
    const float* m_k = (const float*)d_in[6];
    const float* m_v = (const float*)d_in[7];
    const float* m_a = (const float*)d_in[8];
    const float* m_g = (const float*)d_in[9];

    const float *w0, *w1, *w2, *a0, *a1, *a2, *v0, *v1, *v2, *g1, *g2, *k_k, *k_a, *r_k;
    if (in_sizes[11] == C) {
        w0 = (const float*)d_in[10]; a0 = (const float*)d_in[11];
        v0 = (const float*)d_in[12]; k_k = (const float*)d_in[13];
        k_a = (const float*)d_in[14];
        w1 = (const float*)d_in[15]; w2 = (const float*)d_in[16];
        a1 = (const float*)d_in[17]; a2 = (const float*)d_in[18];
        v1 = (const float*)d_in[19]; v2 = (const float*)d_in[20];
        g1 = (const float*)d_in[21]; g2 = (const float*)d_in[22];
        r_k = (const float*)d_in[23];
    } else {
        w0 = (const float*)d_in[10]; w1 = (const float*)d_in[11];
        w2 = (const float*)d_in[12];
        a0 = (const float*)d_in[13]; a1 = (const float*)d_in[14];
        a2 = (const float*)d_in[15];
        v0 = (const float*)d_in[16]; v1 = (const float*)d_in[17];
        v2 = (const float*)d_in[18];
        g1 = (const float*)d_in[19]; g2 = (const float*)d_in[20];
        k_k = (const float*)d_in[21]; k_a = (const float*)d_in[22];
        r_k = (const float*)d_in[23];
    }

    const float* Wr = (const float*)d_in[24];
    const float* Wk = (const float*)d_in[25];
    const float* Wv = (const float*)d_in[26];
    const float* Wo = (const float*)d_in[27];
    const float* lnw = (const float*)d_in[28];
    const float* lnb = (const float*)d_in[29];
    const int*   cu  = (const int*)d_in[30];
    const int ncu = in_sizes[30];
    float* out = (float*)d_out;

    float* s = nullptr;
    cudaGetSymbolAddress((void**)&s, g_scratch);
    const size_t P = (size_t)T * C;
    float* xr = s;          float* xw = s + P;      float* xk = s + 2 * P;
    float* xv = s + 3 * P;  float* xa = s + 4 * P;  float* xg = s + 5 * P;
    float* rb = s + 6 * P;  float* kb = s + 7 * P;  float* vbuf = s + 8 * P;
    float* ewb = s + 9 * P; float* ab = s + 10 * P; float* gbuf = s + 11 * P;
    float* aab = s + 12 * P; float* bbb = s + 13 * P; float* kadj = s + 14 * P;
    float* yb = s + 15 * P;  float* zb = s + 16 * P;
    float* hw = s + 17 * P;
    float* ha = hw + (size_t)T * 64;
    float* hv = ha + (size_t)T * 64;
    float* hg = hv + (size_t)T * 32;

    const int GEMM_SMEM = 2 * 4 * STAGE_U32 * 4;   // 81920 B
    static int smem_set = 0;
    if (!smem_set) {
        cudaFuncSetAttribute(k_gemm_mma, cudaFuncAttributeMaxDynamicSharedMemorySize,
                             GEMM_SMEM);
        smem_set = 1;
    }

    k_shift_mix<<<T, 256>>>(x, x_prev, cu, ncu, m_r, m_w, m_k, m_v, m_a, m_g,
                            xr, xw, xk, xv, xa, xg);

    dim3 gemm_grid(C / 128, T / 128);
    k_gemm_mma<<<gemm_grid, 256, GEMM_SMEM>>>(xr, Wr, rb);
    k_gemm_mma<<<gemm_grid, 256, GEMM_SMEM>>>(xk, Wk, kb);
    k_gemm_mma<<<gemm_grid, 256, GEMM_SMEM>>>(xv, Wv, vbuf);

    k_stage1<64, 1><<<T / 32, 256>>>(xw, w1, hw);
    k_stage1<64, 0><<<T / 32, 256>>>(xa, a1, ha);
    k_stage1<32, 0><<<T / 32, 256>>>(xv, v1, hv);
    k_stage1<128, 2><<<T / 32, 256>>>(xg, g1, hg);

    dim3 s2grid(C / 128, T / 16);
    k_stage2<64, 0><<<s2grid, 128>>>(hw, w2, w0, nullptr, nullptr, ewb);
    k_stage2<64, 1><<<s2grid, 128>>>(ha, a2, a0, nullptr, nullptr, ab);
    k_stage2<32, 2><<<s2grid, 128>>>(hv, v2, v0, vbuf, v_first, vbuf);
    k_stage2<128, 3><<<s2grid, 128>>>(hg, g2, nullptr, nullptr, nullptr, gbuf);

    k_prep<<<T, 256>>>(kb, ab, k_k, k_a, aab, bbb, kadj);

    k_scan<<<dim3(NH, 16), 32>>>(rb, ewb, aab, bbb, kadj, vbuf, S0, yb);

    k_gn<<<T, 256>>>(yb, rb, kadj, vbuf, gbuf, r_k, lnw, lnb, zb);

    k_gemm_mma<<<gemm_grid, 256, GEMM_SMEM>>>(zb, Wo, out);
}